// round 6
// baseline (speedup 1.0000x reference)
#include <cuda_runtime.h>
#include <math.h>

#define NH   12
#define D    64
#define SEQ  1024
#define BAT  4
#define HID  768
#define BS   4096      // BAT*SEQ
#define POS  512       // 2*span
#define SPAN 256

// -------- scratch (static device memory; no allocations) --------
__device__ float g_q[BS * HID];
__device__ float g_k[BS * HID];
__device__ float g_v[BS * HID];          // TRANSPOSED per head: [b][h][d][s]
__device__ float g_ctx[BS * HID];
__device__ float g_pre[BS * HID];
__device__ float g_posk[POS * HID];
__device__ float g_posq[POS * HID];
__device__ float g_c2p[(size_t)NH * BS * POS];    // [h][b*S+s][512]
__device__ float g_p2cT[(size_t)NH * POS * BS];   // [h][bucket][b*S+t]
__device__ int   g_c2pidx[2048];
__device__ int   g_p2cidx[2048];

// -------- relative-position bucket table (matches numpy exactly) --------
__global__ void relb_kernel() {
    int i = blockIdx.x * blockDim.x + threadIdx.x;
    if (i >= 2047) return;
    int rel = i - 1023;
    const int mid = 128;
    int sgn = (rel > 0) - (rel < 0);
    float abs_pos = (rel < mid && rel > -mid) ? (float)(mid - 1) : (float)abs(rel);
    float num32 = logf(abs_pos / 128.0f);
    double log_pos = ceil((double)num32 / log(511.0 / 128.0) * 127.0) + 128.0;
    long long bucket = (abs_pos <= 128.0f) ? (long long)rel
                                           : (long long)(log_pos * (double)sgn);
    int bi = (int)bucket;
    int c = bi + SPAN;  c = c < 0 ? 0 : (c > 2 * SPAN - 1 ? 2 * SPAN - 1 : c);
    int p = -bi + SPAN; p = p < 0 ? 0 : (p > 2 * SPAN - 1 ? 2 * SPAN - 1 : p);
    g_c2pidx[i] = c;
    g_p2cidx[i] = p;
}

// -------- tf32 helpers --------
__device__ __forceinline__ float f2tf(float x) {
    unsigned u;
    asm("cvt.rna.tf32.f32 %0, %1;" : "=r"(u) : "f"(x));
    return __uint_as_float(u);
}

__device__ __forceinline__ void mma_tf32(float* c, const unsigned* a, const unsigned* b) {
    asm volatile(
        "mma.sync.aligned.m16n8k8.row.col.f32.tf32.tf32.f32 "
        "{%0,%1,%2,%3},{%4,%5,%6,%7},{%8,%9},{%0,%1,%2,%3};"
        : "+f"(c[0]), "+f"(c[1]), "+f"(c[2]), "+f"(c[3])
        : "r"(a[0]), "r"(a[1]), "r"(a[2]), "r"(a[3]), "r"(b[0]), "r"(b[1]));
}

__device__ __forceinline__ void cp_async16(unsigned dst, const void* src) {
    asm volatile("cp.async.cg.shared.global [%0], [%1], 16;\n" :: "r"(dst), "l"(src));
}

// -------- generic tensor-core NT GEMM body (unchanged) --------
template<int EPI, int TM>
__device__ __forceinline__ void gemm_body(
    const float* __restrict__ A, int lda,
    const float* __restrict__ B, int ldb,
    const float* __restrict__ bias,
    const float* __restrict__ resid, int ldr,
    float* __restrict__ C, long long ldc, int K,
    int row0, int col0)
{
    constexpr int MI = TM / 64;
    __shared__ __align__(16) float As[2][TM][20];
    __shared__ __align__(16) float Bs[2][64][20];
    int tid = threadIdx.x;
    int wid = tid >> 5, lane = tid & 31;
    int quad = lane >> 2, qt = lane & 3;
    int wm, wn;
    if (TM == 128) { wm = (wid >> 1) * 32; wn = (wid & 1) * 32; }
    else           { wm = (wid & 3) * 16;  wn = (wid >> 2) * 32; }

    float acc[MI][4][4];
#pragma unroll
    for (int i = 0; i < MI; i++)
#pragma unroll
        for (int j = 0; j < 4; j++)
#pragma unroll
            for (int l = 0; l < 4; l++) acc[i][j][l] = 0.0f;

    const float* Ap = A + ((long long)row0 + (tid >> 2)) * lda + (tid & 3) * 4;
    const float* Bp = B + ((long long)col0 + (tid >> 2)) * ldb + (tid & 3) * 4;

    float4 ra0, ra1, rb;
    auto do_ldg = [&](long long ko) {
        ra0 = *reinterpret_cast<const float4*>(Ap + ko);
        if (TM == 128) ra1 = *reinterpret_cast<const float4*>(Ap + 64LL * lda + ko);
        rb  = *reinterpret_cast<const float4*>(Bp + ko);
    };
    auto do_sts = [&](int bf) {
        int m = tid >> 2, kq = (tid & 3) * 4;
        float4 t;
        t.x = f2tf(ra0.x); t.y = f2tf(ra0.y); t.z = f2tf(ra0.z); t.w = f2tf(ra0.w);
        *reinterpret_cast<float4*>(&As[bf][m][kq]) = t;
        if (TM == 128) {
            t.x = f2tf(ra1.x); t.y = f2tf(ra1.y); t.z = f2tf(ra1.z); t.w = f2tf(ra1.w);
            *reinterpret_cast<float4*>(&As[bf][m + 64][kq]) = t;
        }
        t.x = f2tf(rb.x); t.y = f2tf(rb.y); t.z = f2tf(rb.z); t.w = f2tf(rb.w);
        *reinterpret_cast<float4*>(&Bs[bf][m][kq]) = t;
    };
    auto do_comp = [&](int bf) {
#pragma unroll
        for (int kk = 0; kk < 16; kk += 8) {
            unsigned af[MI][4], bfr[4][2];
#pragma unroll
            for (int mi = 0; mi < MI; mi++) {
                int r = wm + mi * 16 + quad;
                af[mi][0] = __float_as_uint(As[bf][r][kk + qt]);
                af[mi][1] = __float_as_uint(As[bf][r + 8][kk + qt]);
                af[mi][2] = __float_as_uint(As[bf][r][kk + qt + 4]);
                af[mi][3] = __float_as_uint(As[bf][r + 8][kk + qt + 4]);
            }
#pragma unroll
            for (int ni = 0; ni < 4; ni++) {
                int n = wn + ni * 8 + quad;
                bfr[ni][0] = __float_as_uint(Bs[bf][n][kk + qt]);
                bfr[ni][1] = __float_as_uint(Bs[bf][n][kk + qt + 4]);
            }
#pragma unroll
            for (int mi = 0; mi < MI; mi++)
#pragma unroll
                for (int ni = 0; ni < 4; ni++)
                    mma_tf32(acc[mi][ni], af[mi], bfr[ni]);
        }
    };

    int nst = K >> 4;
    do_ldg(0);
    do_sts(0);
    __syncthreads();
    int buf = 0;
    for (int s = 1; s < nst; s++) {
        do_ldg((long long)s * 16);
        do_comp(buf);
        do_sts(buf ^ 1);
        __syncthreads();
        buf ^= 1;
    }
    do_comp(buf);

#pragma unroll
    for (int mi = 0; mi < MI; mi++) {
#pragma unroll
        for (int half = 0; half < 2; half++) {
            long long row = row0 + wm + mi * 16 + quad + half * 8;
#pragma unroll
            for (int ni = 0; ni < 4; ni++) {
                long long col = col0 + wn + ni * 8 + qt * 2;
                float v0 = acc[mi][ni][half * 2 + 0];
                float v1 = acc[mi][ni][half * 2 + 1];
                if (EPI >= 1) { v0 += bias[col]; v1 += bias[col + 1]; }
                if (EPI == 2) {
                    v0 += resid[row * ldr + col];
                    v1 += resid[row * ldr + col + 1];
                }
                if (EPI == 3) {
                    int bb = (int)(row >> 10), ss = (int)(row & 1023);
                    int hh = (int)(col >> 6), dd = (int)(col & 63);
                    C[((((long long)bb * NH + hh) * D + dd) << 10) + ss] = v0;
                    hh = (int)((col + 1) >> 6); dd = (int)((col + 1) & 63);
                    C[((((long long)bb * NH + hh) * D + dd) << 10) + ss] = v1;
                } else {
                    *reinterpret_cast<float2*>(&C[row * ldc + col]) = make_float2(v0, v1);
                }
            }
        }
    }
}

// -------- merged projection kernel --------
__global__ void __launch_bounds__(256) k_proj(
    const float* __restrict__ hs, const float* __restrict__ rel,
    const float* __restrict__ Wq, const float* __restrict__ bq,
    const float* __restrict__ Wk, const float* __restrict__ bk,
    const float* __restrict__ Wv, const float* __restrict__ bv)
{
    int y = blockIdx.y;
    int col0 = blockIdx.x * 64;
    if (y < 32)
        gemm_body<1, 128>(hs, HID, Wq, HID, bq, nullptr, 0, g_q, HID, HID, y * 128, col0);
    else if (y < 64)
        gemm_body<1, 128>(hs, HID, Wk, HID, bk, nullptr, 0, g_k, HID, HID, (y - 32) * 128, col0);
    else if (y < 96)
        gemm_body<3, 128>(hs, HID, Wv, HID, bv, nullptr, 0, g_v, HID, HID, (y - 64) * 128, col0);
    else if (y < 100)
        gemm_body<1, 128>(rel, HID, Wk, HID, bk, nullptr, 0, g_posk, HID, HID, (y - 96) * 128, col0);
    else
        gemm_body<1, 128>(rel, HID, Wq, HID, bq, nullptr, 0, g_posq, HID, HID, (y - 100) * 128, col0);
}

// -------- pos-att: c2p [h][s][bucket] and p2cT [h][bucket][t] --------
__global__ void __launch_bounds__(256) k_posatt() {
    int z = blockIdx.x;
    if (z < 3072) {
        int h = z >> 8, r = z & 255;
        gemm_body<0, 128>(g_q + h * D, HID, g_posk + h * D, HID, nullptr, nullptr, 0,
                          g_c2p + (size_t)h * BS * POS, POS, D,
                          (r >> 3) * 128, (r & 7) * 64);
    } else {
        z -= 3072;
        int h = z >> 8, r = z & 255;
        gemm_body<0, 128>(g_posq + h * D, HID, g_k + h * D, HID, nullptr, nullptr, 0,
                          g_p2cT + (size_t)h * POS * BS, BS, D,
                          (r >> 6) * 128, (r & 63) * 64);
    }
}

// ======== FUSED scores + gathers + softmax, 256 threads (no reg cap) ========
// 8 warps, CTA tile: 16 rows x 1024 cols. Each warp: rows 0-15, cols w*8 within
// each 64-col chunk. k streamed via 4-stage cp.async ring. acc[16][4] in regs.
__global__ void __launch_bounds__(256, 1) k_fused_scores(float* __restrict__ probs) {
    extern __shared__ float dyn[];
    float* Qs = dyn;                        // [16][68]
    float* Ks = dyn + 16 * 68;              // [4][64][68]
    float* red_m = Ks + 4 * 64 * 68;        // [16][8]
    float* red_s = red_m + 128;             // [16][8]

    int s0 = blockIdx.x * 16;
    int bh = blockIdx.y;
    int b = bh / NH, h = bh % NH;
    int tid = threadIdx.x;
    int w = tid >> 5, lane = tid & 31;
    int quad = lane >> 2, qt = lane & 3;
    int wn = w * 8;

    const float* kptr = g_k + ((long long)b * SEQ) * HID + h * D;
    unsigned ks_base = (unsigned)__cvta_generic_to_shared(Ks);

    // cp.async: 4 x 16B per thread per 64x64 stage
    auto issue = [&](int cc) {
        int slot = cc & 3;
        const float* srcb = kptr + (long long)cc * 64 * HID;
#pragma unroll
        for (int j = 0; j < 4; j++) {
            int lin = tid + j * 256;
            int r = lin >> 4, c = (lin & 15) << 2;
            cp_async16(ks_base + (unsigned)(((slot * 64 + r) * 68 + c) * 4),
                       srcb + (long long)r * HID + c);
        }
        asm volatile("cp.async.commit_group;\n");
    };

    issue(0); issue(1); issue(2);

    // load q tile (16x64), tf32-converted: 256 float4, one per thread
    {
        int m = tid >> 4, kq = (tid & 15) * 4;
        float4 t4 = *reinterpret_cast<const float4*>(
            g_q + ((long long)(b * SEQ + s0 + m)) * HID + h * D + kq);
        float4 o;
        o.x = f2tf(t4.x); o.y = f2tf(t4.y); o.z = f2tf(t4.z); o.w = f2tf(t4.w);
        *reinterpret_cast<float4*>(&Qs[m * 68 + kq]) = o;
    }
    __syncthreads();

    // hoist q fragments: 8 k-steps x 4 regs
    unsigned areg[8][4];
#pragma unroll
    for (int ks = 0; ks < 8; ks++) {
        int kk = ks * 8;
        areg[ks][0] = __float_as_uint(Qs[quad * 68 + kk + qt]);
        areg[ks][1] = __float_as_uint(Qs[(quad + 8) * 68 + kk + qt]);
        areg[ks][2] = __float_as_uint(Qs[quad * 68 + kk + qt + 4]);
        areg[ks][3] = __float_as_uint(Qs[(quad + 8) * 68 + kk + qt + 4]);
    }

    float acc[16][4];
#pragma unroll
    for (int f = 0; f < 16; f++)
#pragma unroll
        for (int j = 0; j < 4; j++) acc[f][j] = 0.0f;

#pragma unroll
    for (int c = 0; c < 16; c++) {
        asm volatile("cp.async.wait_group %0;\n" :: "n"(2));
        __syncthreads();
        if (c < 13) issue(c + 3);
        else        asm volatile("cp.async.commit_group;\n");
        int slot = c & 3;
        const float* kb = &Ks[(slot * 64 + wn + quad) * 68];
#pragma unroll
        for (int ks = 0; ks < 8; ks++) {
            unsigned bb[2];
            bb[0] = __float_as_uint(f2tf(kb[ks * 8 + qt]));
            bb[1] = __float_as_uint(f2tf(kb[ks * 8 + qt + 4]));
            mma_tf32(acc[c], areg[ks], bb);
        }
    }

    // ---- epilogue: gathers + scale, row max ----
    const float inv = rsqrtf(192.0f);
    long long c2pb0 = ((long long)h * BS + b * SEQ + s0 + quad) * POS;
    long long c2pb1 = c2pb0 + 8LL * POS;
    long long pTb = (long long)h * POS * BS + (long long)b * SEQ;
    float rmax[2] = {-1e30f, -1e30f};
#pragma unroll
    for (int f = 0; f < 16; f++) {
        int colb = f * 64 + wn + qt * 2;
#pragma unroll
        for (int rh = 0; rh < 2; rh++) {
            int s = s0 + quad + rh * 8;
            long long cb = rh ? c2pb1 : c2pb0;
#pragma unroll
            for (int e = 0; e < 2; e++) {
                int t = colb + e;
                int dlt = s - t + 1023;
                int ci = __ldg(&g_c2pidx[dlt]);
                int pi = __ldg(&g_p2cidx[2046 - dlt]);
                float x = acc[f][rh * 2 + e]
                        + __ldg(&g_c2p[cb + ci])
                        + __ldg(&g_p2cT[pTb + (long long)pi * BS + t]);
                x *= inv;
                acc[f][rh * 2 + e] = x;
                rmax[rh] = fmaxf(rmax[rh], x);
            }
        }
    }
#pragma unroll
    for (int o = 1; o <= 2; o <<= 1) {
        rmax[0] = fmaxf(rmax[0], __shfl_xor_sync(0xffffffffu, rmax[0], o));
        rmax[1] = fmaxf(rmax[1], __shfl_xor_sync(0xffffffffu, rmax[1], o));
    }
    if (qt == 0) { red_m[quad * 8 + w] = rmax[0]; red_m[(quad + 8) * 8 + w] = rmax[1]; }
    __syncthreads();
    float mrow[2];
#pragma unroll
    for (int rh = 0; rh < 2; rh++) {
        float m = red_m[(quad + rh * 8) * 8];
#pragma unroll
        for (int j = 1; j < 8; j++) m = fmaxf(m, red_m[(quad + rh * 8) * 8 + j]);
        mrow[rh] = m;
    }
    float rsum[2] = {0.0f, 0.0f};
#pragma unroll
    for (int f = 0; f < 16; f++)
#pragma unroll
        for (int rh = 0; rh < 2; rh++)
#pragma unroll
            for (int e = 0; e < 2; e++) {
                float v = expf(acc[f][rh * 2 + e] - mrow[rh]);
                acc[f][rh * 2 + e] = v;
                rsum[rh] += v;
            }
#pragma unroll
    for (int o = 1; o <= 2; o <<= 1) {
        rsum[0] += __shfl_xor_sync(0xffffffffu, rsum[0], o);
        rsum[1] += __shfl_xor_sync(0xffffffffu, rsum[1], o);
    }
    if (qt == 0) { red_s[quad * 8 + w] = rsum[0]; red_s[(quad + 8) * 8 + w] = rsum[1]; }
    __syncthreads();
    float rinv[2];
#pragma unroll
    for (int rh = 0; rh < 2; rh++) {
        float sum = 0.0f;
#pragma unroll
        for (int j = 0; j < 8; j++) sum += red_s[(quad + rh * 8) * 8 + j];
        rinv[rh] = 1.0f / sum;
    }
#pragma unroll
    for (int rh = 0; rh < 2; rh++) {
        float* prow = probs + ((long long)bh * SEQ + s0 + quad + rh * 8) * SEQ;
#pragma unroll
        for (int f = 0; f < 16; f++) {
            int colb = f * 64 + wn + qt * 2;
            *reinterpret_cast<float2*>(&prow[colb]) =
                make_float2(acc[f][rh * 2] * rinv[rh], acc[f][rh * 2 + 1] * rinv[rh]);
        }
    }
}

__global__ void __launch_bounds__(256) k_ctx(const float* __restrict__ probs) {
    int z = blockIdx.y;
    int b = z / NH, h = z % NH;
    gemm_body<0, 64>(probs + (size_t)z * SEQ * SEQ, SEQ,
                     g_v + (size_t)z * D * SEQ, SEQ,
                     nullptr, nullptr, 0,
                     g_ctx + (size_t)(b * SEQ) * HID + h * D, HID, SEQ,
                     blockIdx.x * 64, 0);
}

__global__ void __launch_bounds__(256) k_out(const float* __restrict__ hs,
                                             const float* __restrict__ Wo, const float* __restrict__ bo) {
    gemm_body<2, 128>(g_ctx, HID, Wo, HID, bo, hs, HID, g_pre, HID, HID,
                      blockIdx.y * 128, blockIdx.x * 64);
}

// -------- layernorm over rows of g_pre --------
__global__ void ln_kernel(const float* __restrict__ lnw, const float* __restrict__ lnb,
                          float* __restrict__ out) {
    int row = blockIdx.x;
    const float* x = g_pre + (long long)row * HID;
    float* o = out + (long long)row * HID;
    int tid = threadIdx.x;
    __shared__ float red[8];
    float v[3];
    float s = 0.0f;
#pragma unroll
    for (int k = 0; k < 3; k++) {
        v[k] = x[tid + k * 256];
        s += v[k];
    }
#pragma unroll
    for (int o2 = 16; o2; o2 >>= 1) s += __shfl_xor_sync(0xffffffffu, s, o2);
    if ((tid & 31) == 0) red[tid >> 5] = s;
    __syncthreads();
    if (tid == 0) {
        float x2 = 0.0f;
#pragma unroll
        for (int i = 0; i < 8; i++) x2 += red[i];
        red[0] = x2;
    }
    __syncthreads();
    float mu = red[0] / (float)HID;
    __syncthreads();
    float sq = 0.0f;
#pragma unroll
    for (int k = 0; k < 3; k++) {
        float d = v[k] - mu;
        sq += d * d;
    }
#pragma unroll
    for (int o2 = 16; o2; o2 >>= 1) sq += __shfl_xor_sync(0xffffffffu, sq, o2);
    if ((tid & 31) == 0) red[tid >> 5] = sq;
    __syncthreads();
    if (tid == 0) {
        float x2 = 0.0f;
#pragma unroll
        for (int i = 0; i < 8; i++) x2 += red[i];
        red[0] = x2;
    }
    __syncthreads();
    float var = red[0] / (float)HID;
    float rstd = 1.0f / sqrtf(var + 1e-7f);
#pragma unroll
    for (int k = 0; k < 3; k++) {
        int c = tid + k * 256;
        o[c] = lnw[c] * (v[k] - mu) * rstd + lnb[c];
    }
}

extern "C" void kernel_launch(void* const* d_in, const int* in_sizes, int n_in,
                              void* d_out, int out_size) {
    const float* hs  = (const float*)d_in[0];
    const float* rel = (const float*)d_in[1];
    const float* Wq  = (const float*)d_in[2];
    const float* bq  = (const float*)d_in[3];
    const float* Wk  = (const float*)d_in[4];
    const float* bk  = (const float*)d_in[5];
    const float* Wv  = (const float*)d_in[6];
    const float* bv  = (const float*)d_in[7];
    const float* Wo  = (const float*)d_in[8];
    const float* bo  = (const float*)d_in[9];
    const float* lnw = (const float*)d_in[10];
    const float* lnb = (const float*)d_in[11];

    float* out   = (float*)d_out;
    float* probs = out + (size_t)BS * HID;

    const int FUSED_SMEM = (16 * 68 + 4 * 64 * 68 + 256) * 4;   // 75008 bytes
    cudaFuncSetAttribute(k_fused_scores, cudaFuncAttributeMaxDynamicSharedMemorySize, FUSED_SMEM);

    relb_kernel<<<8, 256>>>();
    k_proj<<<dim3(HID / 64, 104), 256>>>(hs, rel, Wq, bq, Wk, bk, Wv, bv);
    k_posatt<<<6144, 256>>>();
    k_fused_scores<<<dim3(SEQ / 16, BAT * NH), 256, FUSED_SMEM>>>(probs);
    k_ctx<<<dim3(SEQ / 64, BAT * NH), 256>>>(probs);
    k_out<<<dim3(HID / 64, BS / 128), 256>>>(hs, Wo, bo);
    ln_kernel<<<BS, 256>>>(lnw, lnb, out);
}

// round 7
// speedup vs baseline: 1.0527x; 1.0527x over previous
#include <cuda_runtime.h>
#include <math.h>

#define NH   12
#define D    64
#define SEQ  1024
#define BAT  4
#define HID  768
#define BS   4096      // BAT*SEQ
#define POS  512       // 2*span
#define SPAN 256

// -------- scratch (static device memory; no allocations) --------
__device__ float g_q[BS * HID];
__device__ float g_k[BS * HID];
__device__ float g_v[BS * HID];          // TRANSPOSED per head: [b][h][d][s]
__device__ float g_ctx[BS * HID];
__device__ float g_pre[BS * HID];
__device__ float g_posk[POS * HID];
__device__ float g_posq[POS * HID];
__device__ float g_c2p[(size_t)NH * BS * POS];    // [h][b*S+s][512]
__device__ float g_p2cT[(size_t)NH * POS * BS];   // [h][bucket][b*S+t]
__device__ int   g_c2pidx[2048];
__device__ int   g_p2cidx[2048];

// -------- relative-position bucket table (matches numpy exactly) --------
__global__ void relb_kernel() {
    int i = blockIdx.x * blockDim.x + threadIdx.x;
    if (i >= 2047) return;
    int rel = i - 1023;
    const int mid = 128;
    int sgn = (rel > 0) - (rel < 0);
    float abs_pos = (rel < mid && rel > -mid) ? (float)(mid - 1) : (float)abs(rel);
    float num32 = logf(abs_pos / 128.0f);
    double log_pos = ceil((double)num32 / log(511.0 / 128.0) * 127.0) + 128.0;
    long long bucket = (abs_pos <= 128.0f) ? (long long)rel
                                           : (long long)(log_pos * (double)sgn);
    int bi = (int)bucket;
    int c = bi + SPAN;  c = c < 0 ? 0 : (c > 2 * SPAN - 1 ? 2 * SPAN - 1 : c);
    int p = -bi + SPAN; p = p < 0 ? 0 : (p > 2 * SPAN - 1 ? 2 * SPAN - 1 : p);
    g_c2pidx[i] = c;
    g_p2cidx[i] = p;
}

// -------- tf32 helpers --------
__device__ __forceinline__ float f2tf(float x) {
    unsigned u;
    asm("cvt.rna.tf32.f32 %0, %1;" : "=r"(u) : "f"(x));
    return __uint_as_float(u);
}

__device__ __forceinline__ void mma_tf32(float* c, const unsigned* a, const unsigned* b) {
    asm volatile(
        "mma.sync.aligned.m16n8k8.row.col.f32.tf32.tf32.f32 "
        "{%0,%1,%2,%3},{%4,%5,%6,%7},{%8,%9},{%0,%1,%2,%3};"
        : "+f"(c[0]), "+f"(c[1]), "+f"(c[2]), "+f"(c[3])
        : "r"(a[0]), "r"(a[1]), "r"(a[2]), "r"(a[3]), "r"(b[0]), "r"(b[1]));
}

__device__ __forceinline__ void cp_async16(unsigned dst, const void* src) {
    asm volatile("cp.async.cg.shared.global [%0], [%1], 16;\n" :: "r"(dst), "l"(src));
}

// -------- generic tensor-core NT GEMM body (unchanged) --------
template<int EPI, int TM>
__device__ __forceinline__ void gemm_body(
    const float* __restrict__ A, int lda,
    const float* __restrict__ B, int ldb,
    const float* __restrict__ bias,
    const float* __restrict__ resid, int ldr,
    float* __restrict__ C, long long ldc, int K,
    int row0, int col0)
{
    constexpr int MI = TM / 64;
    __shared__ __align__(16) float As[2][TM][20];
    __shared__ __align__(16) float Bs[2][64][20];
    int tid = threadIdx.x;
    int wid = tid >> 5, lane = tid & 31;
    int quad = lane >> 2, qt = lane & 3;
    int wm, wn;
    if (TM == 128) { wm = (wid >> 1) * 32; wn = (wid & 1) * 32; }
    else           { wm = (wid & 3) * 16;  wn = (wid >> 2) * 32; }

    float acc[MI][4][4];
#pragma unroll
    for (int i = 0; i < MI; i++)
#pragma unroll
        for (int j = 0; j < 4; j++)
#pragma unroll
            for (int l = 0; l < 4; l++) acc[i][j][l] = 0.0f;

    const float* Ap = A + ((long long)row0 + (tid >> 2)) * lda + (tid & 3) * 4;
    const float* Bp = B + ((long long)col0 + (tid >> 2)) * ldb + (tid & 3) * 4;

    float4 ra0, ra1, rb;
    auto do_ldg = [&](long long ko) {
        ra0 = *reinterpret_cast<const float4*>(Ap + ko);
        if (TM == 128) ra1 = *reinterpret_cast<const float4*>(Ap + 64LL * lda + ko);
        rb  = *reinterpret_cast<const float4*>(Bp + ko);
    };
    auto do_sts = [&](int bf) {
        int m = tid >> 2, kq = (tid & 3) * 4;
        float4 t;
        t.x = f2tf(ra0.x); t.y = f2tf(ra0.y); t.z = f2tf(ra0.z); t.w = f2tf(ra0.w);
        *reinterpret_cast<float4*>(&As[bf][m][kq]) = t;
        if (TM == 128) {
            t.x = f2tf(ra1.x); t.y = f2tf(ra1.y); t.z = f2tf(ra1.z); t.w = f2tf(ra1.w);
            *reinterpret_cast<float4*>(&As[bf][m + 64][kq]) = t;
        }
        t.x = f2tf(rb.x); t.y = f2tf(rb.y); t.z = f2tf(rb.z); t.w = f2tf(rb.w);
        *reinterpret_cast<float4*>(&Bs[bf][m][kq]) = t;
    };
    auto do_comp = [&](int bf) {
#pragma unroll
        for (int kk = 0; kk < 16; kk += 8) {
            unsigned af[MI][4], bfr[4][2];
#pragma unroll
            for (int mi = 0; mi < MI; mi++) {
                int r = wm + mi * 16 + quad;
                af[mi][0] = __float_as_uint(As[bf][r][kk + qt]);
                af[mi][1] = __float_as_uint(As[bf][r + 8][kk + qt]);
                af[mi][2] = __float_as_uint(As[bf][r][kk + qt + 4]);
                af[mi][3] = __float_as_uint(As[bf][r + 8][kk + qt + 4]);
            }
#pragma unroll
            for (int ni = 0; ni < 4; ni++) {
                int n = wn + ni * 8 + quad;
                bfr[ni][0] = __float_as_uint(Bs[bf][n][kk + qt]);
                bfr[ni][1] = __float_as_uint(Bs[bf][n][kk + qt + 4]);
            }
#pragma unroll
            for (int mi = 0; mi < MI; mi++)
#pragma unroll
                for (int ni = 0; ni < 4; ni++)
                    mma_tf32(acc[mi][ni], af[mi], bfr[ni]);
        }
    };

    int nst = K >> 4;
    do_ldg(0);
    do_sts(0);
    __syncthreads();
    int buf = 0;
    for (int s = 1; s < nst; s++) {
        do_ldg((long long)s * 16);
        do_comp(buf);
        do_sts(buf ^ 1);
        __syncthreads();
        buf ^= 1;
    }
    do_comp(buf);

#pragma unroll
    for (int mi = 0; mi < MI; mi++) {
#pragma unroll
        for (int half = 0; half < 2; half++) {
            long long row = row0 + wm + mi * 16 + quad + half * 8;
#pragma unroll
            for (int ni = 0; ni < 4; ni++) {
                long long col = col0 + wn + ni * 8 + qt * 2;
                float v0 = acc[mi][ni][half * 2 + 0];
                float v1 = acc[mi][ni][half * 2 + 1];
                if (EPI >= 1) { v0 += bias[col]; v1 += bias[col + 1]; }
                if (EPI == 2) {
                    v0 += resid[row * ldr + col];
                    v1 += resid[row * ldr + col + 1];
                }
                if (EPI == 3) {
                    int bb = (int)(row >> 10), ss = (int)(row & 1023);
                    int hh = (int)(col >> 6), dd = (int)(col & 63);
                    C[((((long long)bb * NH + hh) * D + dd) << 10) + ss] = v0;
                    hh = (int)((col + 1) >> 6); dd = (int)((col + 1) & 63);
                    C[((((long long)bb * NH + hh) * D + dd) << 10) + ss] = v1;
                } else {
                    *reinterpret_cast<float2*>(&C[row * ldc + col]) = make_float2(v0, v1);
                }
            }
        }
    }
}

// -------- merged projection kernel --------
__global__ void __launch_bounds__(256) k_proj(
    const float* __restrict__ hs, const float* __restrict__ rel,
    const float* __restrict__ Wq, const float* __restrict__ bq,
    const float* __restrict__ Wk, const float* __restrict__ bk,
    const float* __restrict__ Wv, const float* __restrict__ bv)
{
    int y = blockIdx.y;
    int col0 = blockIdx.x * 64;
    if (y < 32)
        gemm_body<1, 128>(hs, HID, Wq, HID, bq, nullptr, 0, g_q, HID, HID, y * 128, col0);
    else if (y < 64)
        gemm_body<1, 128>(hs, HID, Wk, HID, bk, nullptr, 0, g_k, HID, HID, (y - 32) * 128, col0);
    else if (y < 96)
        gemm_body<3, 128>(hs, HID, Wv, HID, bv, nullptr, 0, g_v, HID, HID, (y - 64) * 128, col0);
    else if (y < 100)
        gemm_body<1, 128>(rel, HID, Wk, HID, bk, nullptr, 0, g_posk, HID, HID, (y - 96) * 128, col0);
    else
        gemm_body<1, 128>(rel, HID, Wq, HID, bq, nullptr, 0, g_posq, HID, HID, (y - 100) * 128, col0);
}

// -------- pos-att: c2p [h][s][bucket] and p2cT [h][bucket][t] --------
__global__ void __launch_bounds__(256) k_posatt() {
    int z = blockIdx.x;
    if (z < 3072) {
        int h = z >> 8, r = z & 255;
        gemm_body<0, 128>(g_q + h * D, HID, g_posk + h * D, HID, nullptr, nullptr, 0,
                          g_c2p + (size_t)h * BS * POS, POS, D,
                          (r >> 3) * 128, (r & 7) * 64);
    } else {
        z -= 3072;
        int h = z >> 8, r = z & 255;
        gemm_body<0, 128>(g_posq + h * D, HID, g_k + h * D, HID, nullptr, nullptr, 0,
                          g_p2cT + (size_t)h * POS * BS, BS, D,
                          (r >> 6) * 128, (r & 63) * 64);
    }
}

// ======== FUSED scores + gathers + softmax + ctx (flash-style) ========
// 512 threads = 16 warps (2 m x 8 n). CTA tile: 32 rows x 1024 cols.
// Phase 1: QK^T via cp.async ring. Phase 2: softmax epilogue (c2p from smem).
// Phase 3: stream v through the SAME ring; stage probs chunks in smem; ctx MMA.
// probs written exactly once; k_ctx eliminated.
__global__ void __launch_bounds__(512, 1) k_fused(float* __restrict__ probs) {
    extern __shared__ float dyn[];
    float* Qs   = dyn;                        // [32][68]
    float* Ks   = Qs + 32 * 68;               // [4][64][68] ring (k, then v)
    float* Ps   = Ks + 4 * 64 * 68;           // [32][68] probs chunk staging
    float* c2ps = Ps + 32 * 68;               // [32][512]
    float* red_m = c2ps + 32 * 512;           // [32][8]
    float* red_s = red_m + 256;               // [32][8]

    int s0 = blockIdx.x * 32;
    int bh = blockIdx.y;
    int b = bh / NH, h = bh % NH;
    int tid = threadIdx.x;
    int w = tid >> 5, lane = tid & 31;
    int quad = lane >> 2, qt = lane & 3;
    int wm = (w >> 3) * 16;
    int wn = (w & 7) * 8;
    int nw = w & 7;

    const float* kptr = g_k + ((long long)b * SEQ) * HID + h * D;
    const float* vptr = g_v + (size_t)bh * D * SEQ;
    unsigned ks_base = (unsigned)__cvta_generic_to_shared(Ks);

    int r0 = tid >> 4, c0 = (tid & 15) << 2;
    int r1 = (tid + 512) >> 4, c1 = ((tid + 512) & 15) << 2;

    auto issue_k = [&](int cc) {
        int slot = cc & 3;
        const float* srcb = kptr + (long long)cc * 64 * HID;
        cp_async16(ks_base + (unsigned)(((slot * 64 + r0) * 68 + c0) * 4),
                   srcb + (long long)r0 * HID + c0);
        cp_async16(ks_base + (unsigned)(((slot * 64 + r1) * 68 + c1) * 4),
                   srcb + (long long)r1 * HID + c1);
        asm volatile("cp.async.commit_group;\n");
    };
    auto issue_v = [&](int cc) {
        int slot = cc & 3;
        const float* srcb = vptr + cc * 64;
        cp_async16(ks_base + (unsigned)(((slot * 64 + r0) * 68 + c0) * 4),
                   srcb + (long long)r0 * SEQ + c0);
        cp_async16(ks_base + (unsigned)(((slot * 64 + r1) * 68 + c1) * 4),
                   srcb + (long long)r1 * SEQ + c1);
        asm volatile("cp.async.commit_group;\n");
    };

    issue_k(0); issue_k(1); issue_k(2);

    // q tile (32x64) tf32 into smem: one float4 per thread
    {
        int m = tid >> 4, kq = (tid & 15) * 4;
        float4 t4 = *reinterpret_cast<const float4*>(
            g_q + ((long long)(b * SEQ + s0 + m)) * HID + h * D + kq);
        float4 o;
        o.x = f2tf(t4.x); o.y = f2tf(t4.y); o.z = f2tf(t4.z); o.w = f2tf(t4.w);
        *reinterpret_cast<float4*>(&Qs[m * 68 + kq]) = o;
    }
    // c2p rows for this CTA (32 x 512), coalesced
#pragma unroll
    for (int j = 0; j < 8; j++) {
        int lin = tid + j * 512;
        int r = lin >> 7, c = (lin & 127) << 2;
        *reinterpret_cast<float4*>(&c2ps[r * 512 + c]) =
            *reinterpret_cast<const float4*>(
                g_c2p + ((long long)h * BS + b * SEQ + s0 + r) * POS + c);
    }
    __syncthreads();

    // hoist q fragments
    unsigned areg[8][4];
#pragma unroll
    for (int ks = 0; ks < 8; ks++) {
        int kk = ks * 8;
        areg[ks][0] = __float_as_uint(Qs[(wm + quad) * 68 + kk + qt]);
        areg[ks][1] = __float_as_uint(Qs[(wm + quad + 8) * 68 + kk + qt]);
        areg[ks][2] = __float_as_uint(Qs[(wm + quad) * 68 + kk + qt + 4]);
        areg[ks][3] = __float_as_uint(Qs[(wm + quad + 8) * 68 + kk + qt + 4]);
    }

    float acc[16][4];
#pragma unroll
    for (int f = 0; f < 16; f++)
#pragma unroll
        for (int j = 0; j < 4; j++) acc[f][j] = 0.0f;

#pragma unroll
    for (int c = 0; c < 16; c++) {
        asm volatile("cp.async.wait_group %0;\n" :: "n"(2));
        __syncthreads();
        if (c < 13) issue_k(c + 3);
        else        asm volatile("cp.async.commit_group;\n");
        int slot = c & 3;
        const float* kb = &Ks[(slot * 64 + wn + quad) * 68];
#pragma unroll
        for (int ks = 0; ks < 8; ks++) {
            unsigned bb[2];
            bb[0] = __float_as_uint(f2tf(kb[ks * 8 + qt]));
            bb[1] = __float_as_uint(f2tf(kb[ks * 8 + qt + 4]));
            mma_tf32(acc[c], areg[ks], bb);
        }
    }

    // ---- softmax epilogue: gathers (c2p from smem) + scale, max/sum ----
    const float inv = rsqrtf(192.0f);
    int sl0 = wm + quad;
    long long pTb = (long long)h * POS * BS + (long long)b * SEQ;
    float rmax[2] = {-1e30f, -1e30f};
#pragma unroll
    for (int f = 0; f < 16; f++) {
        int colb = f * 64 + wn + qt * 2;
#pragma unroll
        for (int rh = 0; rh < 2; rh++) {
            int s = s0 + sl0 + rh * 8;
#pragma unroll
            for (int e = 0; e < 2; e++) {
                int t = colb + e;
                int dlt = s - t + 1023;
                int ci = __ldg(&g_c2pidx[dlt]);
                int pi = __ldg(&g_p2cidx[2046 - dlt]);
                float x = acc[f][rh * 2 + e]
                        + c2ps[(sl0 + rh * 8) * 512 + ci]
                        + __ldg(&g_p2cT[pTb + (long long)pi * BS + t]);
                x *= inv;
                acc[f][rh * 2 + e] = x;
                rmax[rh] = fmaxf(rmax[rh], x);
            }
        }
    }
#pragma unroll
    for (int o = 1; o <= 2; o <<= 1) {
        rmax[0] = fmaxf(rmax[0], __shfl_xor_sync(0xffffffffu, rmax[0], o));
        rmax[1] = fmaxf(rmax[1], __shfl_xor_sync(0xffffffffu, rmax[1], o));
    }
    if (qt == 0) { red_m[sl0 * 8 + nw] = rmax[0]; red_m[(sl0 + 8) * 8 + nw] = rmax[1]; }
    __syncthreads();
    float mrow[2];
#pragma unroll
    for (int rh = 0; rh < 2; rh++) {
        float m = red_m[(sl0 + rh * 8) * 8];
#pragma unroll
        for (int j = 1; j < 8; j++) m = fmaxf(m, red_m[(sl0 + rh * 8) * 8 + j]);
        mrow[rh] = m;
    }
    float rsum[2] = {0.0f, 0.0f};
#pragma unroll
    for (int f = 0; f < 16; f++)
#pragma unroll
        for (int rh = 0; rh < 2; rh++)
#pragma unroll
            for (int e = 0; e < 2; e++) {
                float v = expf(acc[f][rh * 2 + e] - mrow[rh]);
                acc[f][rh * 2 + e] = v;
                rsum[rh] += v;
            }
#pragma unroll
    for (int o = 1; o <= 2; o <<= 1) {
        rsum[0] += __shfl_xor_sync(0xffffffffu, rsum[0], o);
        rsum[1] += __shfl_xor_sync(0xffffffffu, rsum[1], o);
    }
    if (qt == 0) { red_s[sl0 * 8 + nw] = rsum[0]; red_s[(sl0 + 8) * 8 + nw] = rsum[1]; }
    __syncthreads();
    float rinv[2];
#pragma unroll
    for (int rh = 0; rh < 2; rh++) {
        float sum = 0.0f;
#pragma unroll
        for (int j = 0; j < 8; j++) sum += red_s[(sl0 + rh * 8) * 8 + j];
        rinv[rh] = 1.0f / sum;
    }

    // ---- ctx phase: stream v through ring, stage probs chunks via Ps ----
    issue_v(0); issue_v(1); issue_v(2);
    float accc[4] = {0.0f, 0.0f, 0.0f, 0.0f};
    float* prow0 = probs + ((long long)bh * SEQ + s0 + sl0) * SEQ;
    float* prow1 = prow0 + 8LL * SEQ;
#pragma unroll
    for (int c = 0; c < 16; c++) {
        __syncthreads();                       // prior MMA reads of Ps done
        int colb = c * 64 + wn + qt * 2;
        float p00 = acc[c][0] * rinv[0], p01 = acc[c][1] * rinv[0];
        float p10 = acc[c][2] * rinv[1], p11 = acc[c][3] * rinv[1];
        *reinterpret_cast<float2*>(&prow0[colb]) = make_float2(p00, p01);
        *reinterpret_cast<float2*>(&prow1[colb]) = make_float2(p10, p11);
        int pc = wn + qt * 2;
        Ps[sl0 * 68 + pc]           = f2tf(p00);
        Ps[sl0 * 68 + pc + 1]       = f2tf(p01);
        Ps[(sl0 + 8) * 68 + pc]     = f2tf(p10);
        Ps[(sl0 + 8) * 68 + pc + 1] = f2tf(p11);
        asm volatile("cp.async.wait_group %0;\n" :: "n"(2));
        __syncthreads();                       // Ps visible + v chunk ready
        if (c < 13) issue_v(c + 3);
        else        asm volatile("cp.async.commit_group;\n");
        int slot = c & 3;
        const float* vb = &Ks[(slot * 64 + wn + quad) * 68];
#pragma unroll
        for (int ks = 0; ks < 8; ks++) {
            int kk = ks * 8;
            unsigned af[4], bb[2];
            af[0] = __float_as_uint(Ps[(wm + quad) * 68 + kk + qt]);
            af[1] = __float_as_uint(Ps[(wm + quad + 8) * 68 + kk + qt]);
            af[2] = __float_as_uint(Ps[(wm + quad) * 68 + kk + qt + 4]);
            af[3] = __float_as_uint(Ps[(wm + quad + 8) * 68 + kk + qt + 4]);
            bb[0] = __float_as_uint(f2tf(vb[kk + qt]));
            bb[1] = __float_as_uint(f2tf(vb[kk + qt + 4]));
            mma_tf32(accc, af, bb);
        }
    }
    // ctx store: rows s0+wm+quad(+8), cols h*D + wn + qt*2
    long long crow = ((long long)(b * SEQ + s0 + wm + quad)) * HID + h * D + wn + qt * 2;
    *reinterpret_cast<float2*>(&g_ctx[crow]) = make_float2(accc[0], accc[1]);
    *reinterpret_cast<float2*>(&g_ctx[crow + 8LL * HID]) = make_float2(accc[2], accc[3]);
}

__global__ void __launch_bounds__(256) k_out(const float* __restrict__ hs,
                                             const float* __restrict__ Wo, const float* __restrict__ bo) {
    gemm_body<2, 128>(g_ctx, HID, Wo, HID, bo, hs, HID, g_pre, HID, HID,
                      blockIdx.y * 128, blockIdx.x * 64);
}

// -------- layernorm over rows of g_pre --------
__global__ void ln_kernel(const float* __restrict__ lnw, const float* __restrict__ lnb,
                          float* __restrict__ out) {
    int row = blockIdx.x;
    const float* x = g_pre + (long long)row * HID;
    float* o = out + (long long)row * HID;
    int tid = threadIdx.x;
    __shared__ float red[8];
    float v[3];
    float s = 0.0f;
#pragma unroll
    for (int k = 0; k < 3; k++) {
        v[k] = x[tid + k * 256];
        s += v[k];
    }
#pragma unroll
    for (int o2 = 16; o2; o2 >>= 1) s += __shfl_xor_sync(0xffffffffu, s, o2);
    if ((tid & 31) == 0) red[tid >> 5] = s;
    __syncthreads();
    if (tid == 0) {
        float x2 = 0.0f;
#pragma unroll
        for (int i = 0; i < 8; i++) x2 += red[i];
        red[0] = x2;
    }
    __syncthreads();
    float mu = red[0] / (float)HID;
    __syncthreads();
    float sq = 0.0f;
#pragma unroll
    for (int k = 0; k < 3; k++) {
        float d = v[k] - mu;
        sq += d * d;
    }
#pragma unroll
    for (int o2 = 16; o2; o2 >>= 1) sq += __shfl_xor_sync(0xffffffffu, sq, o2);
    if ((tid & 31) == 0) red[tid >> 5] = sq;
    __syncthreads();
    if (tid == 0) {
        float x2 = 0.0f;
#pragma unroll
        for (int i = 0; i < 8; i++) x2 += red[i];
        red[0] = x2;
    }
    __syncthreads();
    float var = red[0] / (float)HID;
    float rstd = 1.0f / sqrtf(var + 1e-7f);
#pragma unroll
    for (int k = 0; k < 3; k++) {
        int c = tid + k * 256;
        o[c] = lnw[c] * (v[k] - mu) * rstd + lnb[c];
    }
}

extern "C" void kernel_launch(void* const* d_in, const int* in_sizes, int n_in,
                              void* d_out, int out_size) {
    const float* hs  = (const float*)d_in[0];
    const float* rel = (const float*)d_in[1];
    const float* Wq  = (const float*)d_in[2];
    const float* bq  = (const float*)d_in[3];
    const float* Wk  = (const float*)d_in[4];
    const float* bk  = (const float*)d_in[5];
    const float* Wv  = (const float*)d_in[6];
    const float* bv  = (const float*)d_in[7];
    const float* Wo  = (const float*)d_in[8];
    const float* bo  = (const float*)d_in[9];
    const float* lnw = (const float*)d_in[10];
    const float* lnb = (const float*)d_in[11];

    float* out   = (float*)d_out;
    float* probs = out + (size_t)BS * HID;

    const int FUSED_SMEM = (32 * 68 + 4 * 64 * 68 + 32 * 68 + 32 * 512 + 512) * 4;  // 154624
    cudaFuncSetAttribute(k_fused, cudaFuncAttributeMaxDynamicSharedMemorySize, FUSED_SMEM);

    relb_kernel<<<8, 256>>>();
    k_proj<<<dim3(HID / 64, 104), 256>>>(hs, rel, Wq, bq, Wk, bk, Wv, bv);
    k_posatt<<<6144, 256>>>();
    k_fused<<<dim3(SEQ / 32, BAT * NH), 512, FUSED_SMEM>>>(probs);
    k_out<<<dim3(HID / 64, BS / 128), 256>>>(hs, Wo, bo);
    ln_kernel<<<BS, 256>>>(lnw, lnb, out);
}

// round 8
// speedup vs baseline: 1.0649x; 1.0115x over previous
#include <cuda_runtime.h>
#include <math.h>

#define NH   12
#define D    64
#define SEQ  1024
#define BAT  4
#define HID  768
#define BS   4096      // BAT*SEQ
#define POS  512       // 2*span
#define SPAN 256

// -------- scratch (static device memory; no allocations) --------
__device__ float g_q[BS * HID];
__device__ float g_k[BS * HID];
__device__ float g_v[BS * HID];          // TRANSPOSED per head: [b][h][d][s]
__device__ float g_ctx[BS * HID];
__device__ float g_pre[BS * HID];
__device__ float g_posk[POS * HID];
__device__ float g_posq[POS * HID];
__device__ float g_c2p[(size_t)NH * BS * POS];    // [h][b*S+s][512]
__device__ float g_p2cT[(size_t)NH * POS * BS];   // [h][bucket][b*S+t]
__device__ int   g_c2pidx[2048];
__device__ int   g_p2cidx[2048];

// -------- relative-position bucket table (matches numpy exactly) --------
__global__ void relb_kernel() {
    int i = blockIdx.x * blockDim.x + threadIdx.x;
    if (i >= 2047) return;
    int rel = i - 1023;
    const int mid = 128;
    int sgn = (rel > 0) - (rel < 0);
    float abs_pos = (rel < mid && rel > -mid) ? (float)(mid - 1) : (float)abs(rel);
    float num32 = logf(abs_pos / 128.0f);
    double log_pos = ceil((double)num32 / log(511.0 / 128.0) * 127.0) + 128.0;
    long long bucket = (abs_pos <= 128.0f) ? (long long)rel
                                           : (long long)(log_pos * (double)sgn);
    int bi = (int)bucket;
    int c = bi + SPAN;  c = c < 0 ? 0 : (c > 2 * SPAN - 1 ? 2 * SPAN - 1 : c);
    int p = -bi + SPAN; p = p < 0 ? 0 : (p > 2 * SPAN - 1 ? 2 * SPAN - 1 : p);
    g_c2pidx[i] = c;
    g_p2cidx[i] = p;
}

// -------- tf32 helpers --------
__device__ __forceinline__ float f2tf(float x) {
    unsigned u;
    asm("cvt.rna.tf32.f32 %0, %1;" : "=r"(u) : "f"(x));
    return __uint_as_float(u);
}
__device__ __forceinline__ unsigned f2tfu(float x) {
    unsigned u;
    asm("cvt.rna.tf32.f32 %0, %1;" : "=r"(u) : "f"(x));
    return u;
}

__device__ __forceinline__ void mma_tf32(float* c, const unsigned* a, const unsigned* b) {
    asm volatile(
        "mma.sync.aligned.m16n8k8.row.col.f32.tf32.tf32.f32 "
        "{%0,%1,%2,%3},{%4,%5,%6,%7},{%8,%9},{%0,%1,%2,%3};"
        : "+f"(c[0]), "+f"(c[1]), "+f"(c[2]), "+f"(c[3])
        : "r"(a[0]), "r"(a[1]), "r"(a[2]), "r"(a[3]), "r"(b[0]), "r"(b[1]));
}

__device__ __forceinline__ void cp_async16(unsigned dst, const void* src) {
    asm volatile("cp.async.cg.shared.global [%0], [%1], 16;\n" :: "r"(dst), "l"(src));
}

// ======== generic NT GEMM with 4-stage cp.async ring ========
// C[TM x 64] tile of C = A[M,K] @ B[N,K]^T. 256 threads. BK=16.
// Combined stage: S[slot][ROWS][20], rows [0,TM)=A, [TM,TM+64)=B. tf32 cvt at frag load.
// EPI: 0 plain, 1 +bias, 2 +bias+resid, 3 +bias then scatter to vT [b][h][d][s]
template<int EPI, int TM>
__device__ __forceinline__ void gemm_body(
    const float* __restrict__ A, int lda,
    const float* __restrict__ B, int ldb,
    const float* __restrict__ bias,
    const float* __restrict__ resid, int ldr,
    float* __restrict__ C, long long ldc, int K,
    int row0, int col0)
{
    constexpr int MI = TM / 64;
    constexpr int ROWS = TM + 64;
    constexpr int CP = ROWS / 64;            // float4 copies per thread per stage
    extern __shared__ float S[];             // [4][ROWS][20]
    int tid = threadIdx.x;
    int wid = tid >> 5, lane = tid & 31;
    int quad = lane >> 2, qt = lane & 3;
    int wm, wn;
    if (TM == 128) { wm = (wid >> 1) * 32; wn = (wid & 1) * 32; }
    else           { wm = (wid & 3) * 16;  wn = (wid >> 2) * 32; }

    const float* gsrc[CP];
    unsigned soff[CP];
    unsigned sbase = (unsigned)__cvta_generic_to_shared(S);
#pragma unroll
    for (int j = 0; j < CP; j++) {
        int lin = tid + j * 256;
        int row = lin >> 2, c4 = (lin & 3) * 4;
        soff[j] = row * 20 + c4;
        gsrc[j] = (row < TM) ? A + (long long)(row0 + row) * lda + c4
                             : B + (long long)(col0 + row - TM) * ldb + c4;
    }
    auto issue = [&](int cc) {
        int slot = cc & 3;
        long long k0 = (long long)cc * 16;
#pragma unroll
        for (int j = 0; j < CP; j++)
            cp_async16(sbase + (slot * ROWS * 20 + soff[j]) * 4, gsrc[j] + k0);
        asm volatile("cp.async.commit_group;\n");
    };

    float acc[MI][4][4];
#pragma unroll
    for (int i = 0; i < MI; i++)
#pragma unroll
        for (int j = 0; j < 4; j++)
#pragma unroll
            for (int l = 0; l < 4; l++) acc[i][j][l] = 0.0f;

    auto comp = [&](int slot) {
        const float* Sb = S + slot * ROWS * 20;
#pragma unroll
        for (int kk = 0; kk < 16; kk += 8) {
            unsigned af[MI][4], bfr[4][2];
#pragma unroll
            for (int mi = 0; mi < MI; mi++) {
                int r = wm + mi * 16 + quad;
                af[mi][0] = f2tfu(Sb[r * 20 + kk + qt]);
                af[mi][1] = f2tfu(Sb[(r + 8) * 20 + kk + qt]);
                af[mi][2] = f2tfu(Sb[r * 20 + kk + qt + 4]);
                af[mi][3] = f2tfu(Sb[(r + 8) * 20 + kk + qt + 4]);
            }
#pragma unroll
            for (int ni = 0; ni < 4; ni++) {
                int n = TM + wn + ni * 8 + quad;
                bfr[ni][0] = f2tfu(Sb[n * 20 + kk + qt]);
                bfr[ni][1] = f2tfu(Sb[n * 20 + kk + qt + 4]);
            }
#pragma unroll
            for (int mi = 0; mi < MI; mi++)
#pragma unroll
                for (int ni = 0; ni < 4; ni++)
                    mma_tf32(acc[mi][ni], af[mi], bfr[ni]);
        }
    };

    int nst = K >> 4;
    issue(0); issue(1); issue(2);
    for (int c = 0; c < nst; c++) {
        asm volatile("cp.async.wait_group %0;\n" :: "n"(2));
        __syncthreads();
        if (c + 3 < nst) issue(c + 3);
        else asm volatile("cp.async.commit_group;\n");
        comp(c & 3);
    }

    // epilogue
#pragma unroll
    for (int mi = 0; mi < MI; mi++) {
#pragma unroll
        for (int half = 0; half < 2; half++) {
            long long row = row0 + wm + mi * 16 + quad + half * 8;
#pragma unroll
            for (int ni = 0; ni < 4; ni++) {
                long long col = col0 + wn + ni * 8 + qt * 2;
                float v0 = acc[mi][ni][half * 2 + 0];
                float v1 = acc[mi][ni][half * 2 + 1];
                if (EPI >= 1) { v0 += bias[col]; v1 += bias[col + 1]; }
                if (EPI == 2) {
                    v0 += resid[row * ldr + col];
                    v1 += resid[row * ldr + col + 1];
                }
                if (EPI == 3) {
                    int bb = (int)(row >> 10), ss = (int)(row & 1023);
                    int hh = (int)(col >> 6), dd = (int)(col & 63);
                    C[((((long long)bb * NH + hh) * D + dd) << 10) + ss] = v0;
                    hh = (int)((col + 1) >> 6); dd = (int)((col + 1) & 63);
                    C[((((long long)bb * NH + hh) * D + dd) << 10) + ss] = v1;
                } else {
                    *reinterpret_cast<float2*>(&C[row * ldc + col]) = make_float2(v0, v1);
                }
            }
        }
    }
}

// -------- merged projection kernel --------
__global__ void __launch_bounds__(256) k_proj(
    const float* __restrict__ hs, const float* __restrict__ rel,
    const float* __restrict__ Wq, const float* __restrict__ bq,
    const float* __restrict__ Wk, const float* __restrict__ bk,
    const float* __restrict__ Wv, const float* __restrict__ bv)
{
    int y = blockIdx.y;
    int col0 = blockIdx.x * 64;
    if (y < 32)
        gemm_body<1, 128>(hs, HID, Wq, HID, bq, nullptr, 0, g_q, HID, HID, y * 128, col0);
    else if (y < 64)
        gemm_body<1, 128>(hs, HID, Wk, HID, bk, nullptr, 0, g_k, HID, HID, (y - 32) * 128, col0);
    else if (y < 96)
        gemm_body<3, 128>(hs, HID, Wv, HID, bv, nullptr, 0, g_v, HID, HID, (y - 64) * 128, col0);
    else if (y < 100)
        gemm_body<1, 128>(rel, HID, Wk, HID, bk, nullptr, 0, g_posk, HID, HID, (y - 96) * 128, col0);
    else
        gemm_body<1, 128>(rel, HID, Wq, HID, bq, nullptr, 0, g_posq, HID, HID, (y - 100) * 128, col0);
}

// -------- pos-att: c2p [h][s][bucket] and p2cT [h][bucket][t] --------
__global__ void __launch_bounds__(256) k_posatt() {
    int z = blockIdx.x;
    if (z < 3072) {
        int h = z >> 8, r = z & 255;
        gemm_body<0, 128>(g_q + h * D, HID, g_posk + h * D, HID, nullptr, nullptr, 0,
                          g_c2p + (size_t)h * BS * POS, POS, D,
                          (r >> 3) * 128, (r & 7) * 64);
    } else {
        z -= 3072;
        int h = z >> 8, r = z & 255;
        gemm_body<0, 128>(g_posq + h * D, HID, g_k + h * D, HID, nullptr, nullptr, 0,
                          g_p2cT + (size_t)h * POS * BS, BS, D,
                          (r >> 6) * 128, (r & 63) * 64);
    }
}

// ======== FUSED scores + gathers + softmax -> probs (single write) ========
// 512 threads = 16 warps (2 m x 8 n). CTA tile: 32 rows x 1024 cols.
// k streamed via 4-stage cp.async ring. q-frags reloaded from smem (no reg hoist).
// c2p rows staged in smem.
__global__ void __launch_bounds__(512, 1) k_fused_scores(float* __restrict__ probs) {
    extern __shared__ float dyn[];
    float* Qs    = dyn;                       // [32][68] (tf32-converted)
    float* Ks    = Qs + 32 * 68;              // [4][64][68] ring
    float* c2ps  = Ks + 4 * 64 * 68;          // [32][512]
    float* red_m = c2ps + 32 * 512;           // [32][8]
    float* red_s = red_m + 256;               // [32][8]

    int s0 = blockIdx.x * 32;
    int bh = blockIdx.y;
    int b = bh / NH, h = bh % NH;
    int tid = threadIdx.x;
    int w = tid >> 5, lane = tid & 31;
    int quad = lane >> 2, qt = lane & 3;
    int wm = (w >> 3) * 16;
    int wn = (w & 7) * 8;
    int nw = w & 7;

    const float* kptr = g_k + ((long long)b * SEQ) * HID + h * D;
    unsigned ks_base = (unsigned)__cvta_generic_to_shared(Ks);

    int r0 = tid >> 4, c0 = (tid & 15) << 2;
    int r1 = (tid + 512) >> 4, c1 = ((tid + 512) & 15) << 2;

    auto issue_k = [&](int cc) {
        int slot = cc & 3;
        const float* srcb = kptr + (long long)cc * 64 * HID;
        cp_async16(ks_base + (unsigned)(((slot * 64 + r0) * 68 + c0) * 4),
                   srcb + (long long)r0 * HID + c0);
        cp_async16(ks_base + (unsigned)(((slot * 64 + r1) * 68 + c1) * 4),
                   srcb + (long long)r1 * HID + c1);
        asm volatile("cp.async.commit_group;\n");
    };

    issue_k(0); issue_k(1); issue_k(2);

    // q tile (32x64), tf32-converted, one float4 per thread
    {
        int m = tid >> 4, kq = (tid & 15) * 4;
        float4 t4 = *reinterpret_cast<const float4*>(
            g_q + ((long long)(b * SEQ + s0 + m)) * HID + h * D + kq);
        float4 o;
        o.x = f2tf(t4.x); o.y = f2tf(t4.y); o.z = f2tf(t4.z); o.w = f2tf(t4.w);
        *reinterpret_cast<float4*>(&Qs[m * 68 + kq]) = o;
    }
    // c2p rows for this CTA (32 x 512), coalesced
#pragma unroll
    for (int j = 0; j < 8; j++) {
        int lin = tid + j * 512;
        int r = lin >> 7, c = (lin & 127) << 2;
        *reinterpret_cast<float4*>(&c2ps[r * 512 + c]) =
            *reinterpret_cast<const float4*>(
                g_c2p + ((long long)h * BS + b * SEQ + s0 + r) * POS + c);
    }
    __syncthreads();

    float acc[16][4];
#pragma unroll
    for (int f = 0; f < 16; f++)
#pragma unroll
        for (int j = 0; j < 4; j++) acc[f][j] = 0.0f;

#pragma unroll
    for (int c = 0; c < 16; c++) {
        asm volatile("cp.async.wait_group %0;\n" :: "n"(2));
        __syncthreads();
        if (c < 13) issue_k(c + 3);
        else        asm volatile("cp.async.commit_group;\n");
        int slot = c & 3;
        const float* kb = &Ks[(slot * 64 + wn + quad) * 68];
#pragma unroll
        for (int ks = 0; ks < 8; ks++) {
            int kk = ks * 8;
            unsigned af[4], bb[2];
            af[0] = __float_as_uint(Qs[(wm + quad) * 68 + kk + qt]);
            af[1] = __float_as_uint(Qs[(wm + quad + 8) * 68 + kk + qt]);
            af[2] = __float_as_uint(Qs[(wm + quad) * 68 + kk + qt + 4]);
            af[3] = __float_as_uint(Qs[(wm + quad + 8) * 68 + kk + qt + 4]);
            bb[0] = f2tfu(kb[kk + qt]);
            bb[1] = f2tfu(kb[kk + qt + 4]);
            mma_tf32(acc[c], af, bb);
        }
    }

    // ---- epilogue: gathers (c2p from smem) + scale, row max ----
    const float inv = rsqrtf(192.0f);
    int sl0 = wm + quad;
    long long pTb = (long long)h * POS * BS + (long long)b * SEQ;
    float rmax[2] = {-1e30f, -1e30f};
#pragma unroll
    for (int f = 0; f < 16; f++) {
        int colb = f * 64 + wn + qt * 2;
#pragma unroll
        for (int rh = 0; rh < 2; rh++) {
            int s = s0 + sl0 + rh * 8;
#pragma unroll
            for (int e = 0; e < 2; e++) {
                int t = colb + e;
                int dlt = s - t + 1023;
                int ci = __ldg(&g_c2pidx[dlt]);
                int pi = __ldg(&g_p2cidx[2046 - dlt]);
                float x = acc[f][rh * 2 + e]
                        + c2ps[(sl0 + rh * 8) * 512 + ci]
                        + __ldg(&g_p2cT[pTb + (long long)pi * BS + t]);
                x *= inv;
                acc[f][rh * 2 + e] = x;
                rmax[rh] = fmaxf(rmax[rh], x);
            }
        }
    }
#pragma unroll
    for (int o = 1; o <= 2; o <<= 1) {
        rmax[0] = fmaxf(rmax[0], __shfl_xor_sync(0xffffffffu, rmax[0], o));
        rmax[1] = fmaxf(rmax[1], __shfl_xor_sync(0xffffffffu, rmax[1], o));
    }
    if (qt == 0) { red_m[sl0 * 8 + nw] = rmax[0]; red_m[(sl0 + 8) * 8 + nw] = rmax[1]; }
    __syncthreads();
    float mrow[2];
#pragma unroll
    for (int rh = 0; rh < 2; rh++) {
        float m = red_m[(sl0 + rh * 8) * 8];
#pragma unroll
        for (int j = 1; j < 8; j++) m = fmaxf(m, red_m[(sl0 + rh * 8) * 8 + j]);
        mrow[rh] = m;
    }
    float rsum[2] = {0.0f, 0.0f};
#pragma unroll
    for (int f = 0; f < 16; f++)
#pragma unroll
        for (int rh = 0; rh < 2; rh++)
#pragma unroll
            for (int e = 0; e < 2; e++) {
                float v = expf(acc[f][rh * 2 + e] - mrow[rh]);
                acc[f][rh * 2 + e] = v;
                rsum[rh] += v;
            }
#pragma unroll
    for (int o = 1; o <= 2; o <<= 1) {
        rsum[0] += __shfl_xor_sync(0xffffffffu, rsum[0], o);
        rsum[1] += __shfl_xor_sync(0xffffffffu, rsum[1], o);
    }
    if (qt == 0) { red_s[sl0 * 8 + nw] = rsum[0]; red_s[(sl0 + 8) * 8 + nw] = rsum[1]; }
    __syncthreads();
    float rinv[2];
#pragma unroll
    for (int rh = 0; rh < 2; rh++) {
        float sum = 0.0f;
#pragma unroll
        for (int j = 0; j < 8; j++) sum += red_s[(sl0 + rh * 8) * 8 + j];
        rinv[rh] = 1.0f / sum;
    }
#pragma unroll
    for (int rh = 0; rh < 2; rh++) {
        float* prow = probs + ((long long)bh * SEQ + s0 + sl0 + rh * 8) * SEQ;
#pragma unroll
        for (int f = 0; f < 16; f++) {
            int colb = f * 64 + wn + qt * 2;
            *reinterpret_cast<float2*>(&prow[colb]) =
                make_float2(acc[f][rh * 2] * rinv[rh], acc[f][rh * 2 + 1] * rinv[rh]);
        }
    }
}

__global__ void __launch_bounds__(256) k_ctx(const float* __restrict__ probs) {
    int z = blockIdx.y;
    int b = z / NH, h = z % NH;
    gemm_body<0, 64>(probs + (size_t)z * SEQ * SEQ, SEQ,
                     g_v + (size_t)z * D * SEQ, SEQ,
                     nullptr, nullptr, 0,
                     g_ctx + (size_t)(b * SEQ) * HID + h * D, HID, SEQ,
                     blockIdx.x * 64, 0);
}

__global__ void __launch_bounds__(256) k_out(const float* __restrict__ hs,
                                             const float* __restrict__ Wo, const float* __restrict__ bo) {
    gemm_body<2, 128>(g_ctx, HID, Wo, HID, bo, hs, HID, g_pre, HID, HID,
                      blockIdx.y * 128, blockIdx.x * 64);
}

// -------- layernorm over rows of g_pre --------
__global__ void ln_kernel(const float* __restrict__ lnw, const float* __restrict__ lnb,
                          float* __restrict__ out) {
    int row = blockIdx.x;
    const float* x = g_pre + (long long)row * HID;
    float* o = out + (long long)row * HID;
    int tid = threadIdx.x;
    __shared__ float red[8];
    float v[3];
    float s = 0.0f;
#pragma unroll
    for (int k = 0; k < 3; k++) {
        v[k] = x[tid + k * 256];
        s += v[k];
    }
#pragma unroll
    for (int o2 = 16; o2; o2 >>= 1) s += __shfl_xor_sync(0xffffffffu, s, o2);
    if ((tid & 31) == 0) red[tid >> 5] = s;
    __syncthreads();
    if (tid == 0) {
        float x2 = 0.0f;
#pragma unroll
        for (int i = 0; i < 8; i++) x2 += red[i];
        red[0] = x2;
    }
    __syncthreads();
    float mu = red[0] / (float)HID;
    __syncthreads();
    float sq = 0.0f;
#pragma unroll
    for (int k = 0; k < 3; k++) {
        float d = v[k] - mu;
        sq += d * d;
    }
#pragma unroll
    for (int o2 = 16; o2; o2 >>= 1) sq += __shfl_xor_sync(0xffffffffu, sq, o2);
    if ((tid & 31) == 0) red[tid >> 5] = sq;
    __syncthreads();
    if (tid == 0) {
        float x2 = 0.0f;
#pragma unroll
        for (int i = 0; i < 8; i++) x2 += red[i];
        red[0] = x2;
    }
    __syncthreads();
    float var = red[0] / (float)HID;
    float rstd = 1.0f / sqrtf(var + 1e-7f);
#pragma unroll
    for (int k = 0; k < 3; k++) {
        int c = tid + k * 256;
        o[c] = lnw[c] * (v[k] - mu) * rstd + lnb[c];
    }
}

extern "C" void kernel_launch(void* const* d_in, const int* in_sizes, int n_in,
                              void* d_out, int out_size) {
    const float* hs  = (const float*)d_in[0];
    const float* rel = (const float*)d_in[1];
    const float* Wq  = (const float*)d_in[2];
    const float* bq  = (const float*)d_in[3];
    const float* Wk  = (const float*)d_in[4];
    const float* bk  = (const float*)d_in[5];
    const float* Wv  = (const float*)d_in[6];
    const float* bv  = (const float*)d_in[7];
    const float* Wo  = (const float*)d_in[8];
    const float* bo  = (const float*)d_in[9];
    const float* lnw = (const float*)d_in[10];
    const float* lnb = (const float*)d_in[11];

    float* out   = (float*)d_out;
    float* probs = out + (size_t)BS * HID;

    const int GEMM128_SMEM = 4 * 192 * 20 * 4;   // 61440
    const int GEMM64_SMEM  = 4 * 128 * 20 * 4;   // 40960
    const int FUSED_SMEM = (32 * 68 + 4 * 64 * 68 + 32 * 512 + 512) * 4;  // 145920

    cudaFuncSetAttribute(k_proj,   cudaFuncAttributeMaxDynamicSharedMemorySize, GEMM128_SMEM);
    cudaFuncSetAttribute(k_posatt, cudaFuncAttributeMaxDynamicSharedMemorySize, GEMM128_SMEM);
    cudaFuncSetAttribute(k_out,    cudaFuncAttributeMaxDynamicSharedMemorySize, GEMM128_SMEM);
    cudaFuncSetAttribute(k_ctx,    cudaFuncAttributeMaxDynamicSharedMemorySize, GEMM64_SMEM);
    cudaFuncSetAttribute(k_fused_scores, cudaFuncAttributeMaxDynamicSharedMemorySize, FUSED_SMEM);

    relb_kernel<<<8, 256>>>();
    k_proj<<<dim3(HID / 64, 104), 256, GEMM128_SMEM>>>(hs, rel, Wq, bq, Wk, bk, Wv, bv);
    k_posatt<<<6144, 256, GEMM128_SMEM>>>();
    k_fused_scores<<<dim3(SEQ / 32, BAT * NH), 512, FUSED_SMEM>>>(probs);
    k_ctx<<<dim3(SEQ / 64, BAT * NH), 256, GEMM64_SMEM>>>(probs);
    k_out<<<dim3(HID / 64, BS / 128), 256, GEMM128_SMEM>>>(hs, Wo, bo);
    ln_kernel<<<BS, 256>>>(lnw, lnb, out);
}

// round 9
// speedup vs baseline: 1.1521x; 1.0819x over previous
#include <cuda_runtime.h>
#include <math.h>

#define NH   12
#define D    64
#define SEQ  1024
#define BAT  4
#define HID  768
#define BS   4096      // BAT*SEQ
#define POS  512       // 2*span
#define SPAN 256

// -------- scratch (static device memory; no allocations) --------
__device__ float g_q[BS * HID];                   // tf32-rounded
__device__ float g_k[BS * HID];                   // tf32-rounded
__device__ float g_v[BS * HID];                   // tf32-rounded, [b][h][d][s]
__device__ float g_ctx[BS * HID];                 // tf32-rounded
__device__ float g_pre[BS * HID];
__device__ float g_posk[POS * HID];               // tf32-rounded
__device__ float g_posq[POS * HID];               // tf32-rounded
__device__ float g_c2p[(size_t)NH * BS * POS];    // [h][b*S+s][512]
__device__ float g_p2cT[(size_t)NH * POS * BS];   // [h][bucket][b*S+t]
__device__ int   g_c2pidx[2048];
__device__ int   g_p2cidx[2048];

// -------- relative-position bucket table (matches numpy exactly) --------
__global__ void relb_kernel() {
    int i = blockIdx.x * blockDim.x + threadIdx.x;
    if (i >= 2047) return;
    int rel = i - 1023;
    const int mid = 128;
    int sgn = (rel > 0) - (rel < 0);
    float abs_pos = (rel < mid && rel > -mid) ? (float)(mid - 1) : (float)abs(rel);
    float num32 = logf(abs_pos / 128.0f);
    double log_pos = ceil((double)num32 / log(511.0 / 128.0) * 127.0) + 128.0;
    long long bucket = (abs_pos <= 128.0f) ? (long long)rel
                                           : (long long)(log_pos * (double)sgn);
    int bi = (int)bucket;
    int c = bi + SPAN;  c = c < 0 ? 0 : (c > 2 * SPAN - 1 ? 2 * SPAN - 1 : c);
    int p = -bi + SPAN; p = p < 0 ? 0 : (p > 2 * SPAN - 1 ? 2 * SPAN - 1 : p);
    g_c2pidx[i] = c;
    g_p2cidx[i] = p;
}

// -------- tf32 helpers --------
__device__ __forceinline__ float f2tf(float x) {
    unsigned u;
    asm("cvt.rna.tf32.f32 %0, %1;" : "=r"(u) : "f"(x));
    return __uint_as_float(u);
}
__device__ __forceinline__ unsigned f2tfu(float x) {
    unsigned u;
    asm("cvt.rna.tf32.f32 %0, %1;" : "=r"(u) : "f"(x));
    return u;
}

__device__ __forceinline__ void mma_tf32(float* c, const unsigned* a, const unsigned* b) {
    asm volatile(
        "mma.sync.aligned.m16n8k8.row.col.f32.tf32.tf32.f32 "
        "{%0,%1,%2,%3},{%4,%5,%6,%7},{%8,%9},{%0,%1,%2,%3};"
        : "+f"(c[0]), "+f"(c[1]), "+f"(c[2]), "+f"(c[3])
        : "r"(a[0]), "r"(a[1]), "r"(a[2]), "r"(a[3]), "r"(b[0]), "r"(b[1]));
}

__device__ __forceinline__ void cp_async16(unsigned dst, const void* src) {
    asm volatile("cp.async.cg.shared.global [%0], [%1], 16;\n" :: "r"(dst), "l"(src));
}

// ======== generic NT GEMM with 4-stage cp.async ring ========
// C[TM x 64] tile of C = A[M,K] @ B[N,K]^T. 256 threads. BK=16.
// CVTA/CVTB: convert operand to tf32 at fragment load (false if pre-rounded).
// RND: round outputs to tf32 in epilogue (for tensors consumed as MMA operands).
// EPI: 0 plain, 1 +bias, 2 +bias+resid, 3 +bias then scatter to vT [b][h][d][s]
template<int EPI, int TM, bool CVTA, bool CVTB, bool RND>
__device__ __forceinline__ void gemm_body(
    const float* __restrict__ A, int lda,
    const float* __restrict__ B, int ldb,
    const float* __restrict__ bias,
    const float* __restrict__ resid, int ldr,
    float* __restrict__ C, long long ldc, int K,
    int row0, int col0)
{
    constexpr int MI = TM / 64;
    constexpr int ROWS = TM + 64;
    constexpr int CP = ROWS / 64;
    extern __shared__ float S[];             // [4][ROWS][20]
    int tid = threadIdx.x;
    int wid = tid >> 5, lane = tid & 31;
    int quad = lane >> 2, qt = lane & 3;
    int wm, wn;
    if (TM == 128) { wm = (wid >> 1) * 32; wn = (wid & 1) * 32; }
    else           { wm = (wid & 3) * 16;  wn = (wid >> 2) * 32; }

    const float* gsrc[CP];
    unsigned soff[CP];
    unsigned sbase = (unsigned)__cvta_generic_to_shared(S);
#pragma unroll
    for (int j = 0; j < CP; j++) {
        int lin = tid + j * 256;
        int row = lin >> 2, c4 = (lin & 3) * 4;
        soff[j] = row * 20 + c4;
        gsrc[j] = (row < TM) ? A + (long long)(row0 + row) * lda + c4
                             : B + (long long)(col0 + row - TM) * ldb + c4;
    }
    auto issue = [&](int cc) {
        int slot = cc & 3;
        long long k0 = (long long)cc * 16;
#pragma unroll
        for (int j = 0; j < CP; j++)
            cp_async16(sbase + (slot * ROWS * 20 + soff[j]) * 4, gsrc[j] + k0);
        asm volatile("cp.async.commit_group;\n");
    };

    float acc[MI][4][4];
#pragma unroll
    for (int i = 0; i < MI; i++)
#pragma unroll
        for (int j = 0; j < 4; j++)
#pragma unroll
            for (int l = 0; l < 4; l++) acc[i][j][l] = 0.0f;

    auto ldA = [&](const float* p) -> unsigned {
        return CVTA ? f2tfu(*p) : __float_as_uint(*p);
    };
    auto ldB = [&](const float* p) -> unsigned {
        return CVTB ? f2tfu(*p) : __float_as_uint(*p);
    };

    auto comp = [&](int slot) {
        const float* Sb = S + slot * ROWS * 20;
#pragma unroll
        for (int kk = 0; kk < 16; kk += 8) {
            unsigned af[MI][4], bfr[4][2];
#pragma unroll
            for (int mi = 0; mi < MI; mi++) {
                int r = wm + mi * 16 + quad;
                af[mi][0] = ldA(&Sb[r * 20 + kk + qt]);
                af[mi][1] = ldA(&Sb[(r + 8) * 20 + kk + qt]);
                af[mi][2] = ldA(&Sb[r * 20 + kk + qt + 4]);
                af[mi][3] = ldA(&Sb[(r + 8) * 20 + kk + qt + 4]);
            }
#pragma unroll
            for (int ni = 0; ni < 4; ni++) {
                int n = TM + wn + ni * 8 + quad;
                bfr[ni][0] = ldB(&Sb[n * 20 + kk + qt]);
                bfr[ni][1] = ldB(&Sb[n * 20 + kk + qt + 4]);
            }
#pragma unroll
            for (int mi = 0; mi < MI; mi++)
#pragma unroll
                for (int ni = 0; ni < 4; ni++)
                    mma_tf32(acc[mi][ni], af[mi], bfr[ni]);
        }
    };

    int nst = K >> 4;
    issue(0); issue(1); issue(2);
    for (int c = 0; c < nst; c++) {
        asm volatile("cp.async.wait_group %0;\n" :: "n"(2));
        __syncthreads();
        if (c + 3 < nst) issue(c + 3);
        else asm volatile("cp.async.commit_group;\n");
        comp(c & 3);
    }

    // epilogue
#pragma unroll
    for (int mi = 0; mi < MI; mi++) {
#pragma unroll
        for (int half = 0; half < 2; half++) {
            long long row = row0 + wm + mi * 16 + quad + half * 8;
#pragma unroll
            for (int ni = 0; ni < 4; ni++) {
                long long col = col0 + wn + ni * 8 + qt * 2;
                float v0 = acc[mi][ni][half * 2 + 0];
                float v1 = acc[mi][ni][half * 2 + 1];
                if (EPI >= 1) { v0 += bias[col]; v1 += bias[col + 1]; }
                if (EPI == 2) {
                    v0 += resid[row * ldr + col];
                    v1 += resid[row * ldr + col + 1];
                }
                if (RND) { v0 = f2tf(v0); v1 = f2tf(v1); }
                if (EPI == 3) {
                    int bb = (int)(row >> 10), ss = (int)(row & 1023);
                    int hh = (int)(col >> 6), dd = (int)(col & 63);
                    C[((((long long)bb * NH + hh) * D + dd) << 10) + ss] = v0;
                    hh = (int)((col + 1) >> 6); dd = (int)((col + 1) & 63);
                    C[((((long long)bb * NH + hh) * D + dd) << 10) + ss] = v1;
                } else {
                    *reinterpret_cast<float2*>(&C[row * ldc + col]) = make_float2(v0, v1);
                }
            }
        }
    }
}

// -------- merged projection kernel: outputs tf32-pre-rounded --------
__global__ void __launch_bounds__(256) k_proj(
    const float* __restrict__ hs, const float* __restrict__ rel,
    const float* __restrict__ Wq, const float* __restrict__ bq,
    const float* __restrict__ Wk, const float* __restrict__ bk,
    const float* __restrict__ Wv, const float* __restrict__ bv)
{
    int y = blockIdx.y;
    int col0 = blockIdx.x * 64;
    if (y < 32)
        gemm_body<1, 128, true, true, true>(hs, HID, Wq, HID, bq, nullptr, 0, g_q, HID, HID, y * 128, col0);
    else if (y < 64)
        gemm_body<1, 128, true, true, true>(hs, HID, Wk, HID, bk, nullptr, 0, g_k, HID, HID, (y - 32) * 128, col0);
    else if (y < 96)
        gemm_body<3, 128, true, true, true>(hs, HID, Wv, HID, bv, nullptr, 0, g_v, HID, HID, (y - 64) * 128, col0);
    else if (y < 100)
        gemm_body<1, 128, true, true, true>(rel, HID, Wk, HID, bk, nullptr, 0, g_posk, HID, HID, (y - 96) * 128, col0);
    else
        gemm_body<1, 128, true, true, true>(rel, HID, Wq, HID, bq, nullptr, 0, g_posq, HID, HID, (y - 100) * 128, col0);
}

// -------- pos-att: both operands pre-rounded -> no cvt in loop --------
__global__ void __launch_bounds__(256) k_posatt() {
    int z = blockIdx.x;
    if (z < 3072) {
        int h = z >> 8, r = z & 255;
        gemm_body<0, 128, false, false, false>(g_q + h * D, HID, g_posk + h * D, HID, nullptr, nullptr, 0,
                          g_c2p + (size_t)h * BS * POS, POS, D,
                          (r >> 3) * 128, (r & 7) * 64);
    } else {
        z -= 3072;
        int h = z >> 8, r = z & 255;
        gemm_body<0, 128, false, false, false>(g_posq + h * D, HID, g_k + h * D, HID, nullptr, nullptr, 0,
                          g_p2cT + (size_t)h * POS * BS, BS, D,
                          (r >> 6) * 128, (r & 63) * 64);
    }
}

// ======== FUSED scores + gathers + softmax -> probs (R5 structure, no cvt) ========
// 512 threads = 16 warps (2 m x 8 n). CTA tile: 32 rows x 1024 cols.
// k streamed via 4-stage cp.async ring; q-frags hoisted; gathers via __ldg (L2).
__global__ void __launch_bounds__(512, 1) k_fused_scores(float* __restrict__ probs) {
    extern __shared__ float dyn[];
    float* Qs    = dyn;                       // [32][68] (already tf32)
    float* Ks    = Qs + 32 * 68;              // [4][64][68] ring (already tf32)
    float* red_m = Ks + 4 * 64 * 68;          // [32][8]
    float* red_s = red_m + 256;               // [32][8]

    int s0 = blockIdx.x * 32;
    int bh = blockIdx.y;
    int b = bh / NH, h = bh % NH;
    int tid = threadIdx.x;
    int w = tid >> 5, lane = tid & 31;
    int quad = lane >> 2, qt = lane & 3;
    int wm = (w >> 3) * 16;
    int wn = (w & 7) * 8;
    int nw = w & 7;

    const float* kptr = g_k + ((long long)b * SEQ) * HID + h * D;
    unsigned ks_base = (unsigned)__cvta_generic_to_shared(Ks);

    int r0 = tid >> 4, c0 = (tid & 15) << 2;
    int r1 = (tid + 512) >> 4, c1 = ((tid + 512) & 15) << 2;

    auto issue_k = [&](int cc) {
        int slot = cc & 3;
        const float* srcb = kptr + (long long)cc * 64 * HID;
        cp_async16(ks_base + (unsigned)(((slot * 64 + r0) * 68 + c0) * 4),
                   srcb + (long long)r0 * HID + c0);
        cp_async16(ks_base + (unsigned)(((slot * 64 + r1) * 68 + c1) * 4),
                   srcb + (long long)r1 * HID + c1);
        asm volatile("cp.async.commit_group;\n");
    };

    issue_k(0); issue_k(1); issue_k(2);

    // q tile (32x64) — already tf32-rounded, stage raw
    {
        int m = tid >> 4, kq = (tid & 15) * 4;
        *reinterpret_cast<float4*>(&Qs[m * 68 + kq]) =
            *reinterpret_cast<const float4*>(
                g_q + ((long long)(b * SEQ + s0 + m)) * HID + h * D + kq);
    }
    __syncthreads();

    // hoist q fragments: 8 k-steps x 4 regs
    unsigned areg[8][4];
#pragma unroll
    for (int ks = 0; ks < 8; ks++) {
        int kk = ks * 8;
        areg[ks][0] = __float_as_uint(Qs[(wm + quad) * 68 + kk + qt]);
        areg[ks][1] = __float_as_uint(Qs[(wm + quad + 8) * 68 + kk + qt]);
        areg[ks][2] = __float_as_uint(Qs[(wm + quad) * 68 + kk + qt + 4]);
        areg[ks][3] = __float_as_uint(Qs[(wm + quad + 8) * 68 + kk + qt + 4]);
    }

    float acc[16][4];
#pragma unroll
    for (int f = 0; f < 16; f++)
#pragma unroll
        for (int j = 0; j < 4; j++) acc[f][j] = 0.0f;

#pragma unroll
    for (int c = 0; c < 16; c++) {
        asm volatile("cp.async.wait_group %0;\n" :: "n"(2));
        __syncthreads();
        if (c < 13) issue_k(c + 3);
        else        asm volatile("cp.async.commit_group;\n");
        int slot = c & 3;
        const float* kb = &Ks[(slot * 64 + wn + quad) * 68];
#pragma unroll
        for (int ks = 0; ks < 8; ks++) {
            unsigned bb[2];
            bb[0] = __float_as_uint(kb[ks * 8 + qt]);
            bb[1] = __float_as_uint(kb[ks * 8 + qt + 4]);
            mma_tf32(acc[c], areg[ks], bb);
        }
    }

    // ---- epilogue: gathers via L2 + scale, row max ----
    const float inv = rsqrtf(192.0f);
    int sl0 = wm + quad;
    long long c2pb0 = ((long long)h * BS + b * SEQ + s0 + sl0) * POS;
    long long c2pb1 = c2pb0 + 8LL * POS;
    long long pTb = (long long)h * POS * BS + (long long)b * SEQ;
    float rmax[2] = {-1e30f, -1e30f};
#pragma unroll
    for (int f = 0; f < 16; f++) {
        int colb = f * 64 + wn + qt * 2;
#pragma unroll
        for (int rh = 0; rh < 2; rh++) {
            int s = s0 + sl0 + rh * 8;
            long long cb = rh ? c2pb1 : c2pb0;
#pragma unroll
            for (int e = 0; e < 2; e++) {
                int t = colb + e;
                int dlt = s - t + 1023;
                int ci = __ldg(&g_c2pidx[dlt]);
                int pi = __ldg(&g_p2cidx[2046 - dlt]);
                float x = acc[f][rh * 2 + e]
                        + __ldg(&g_c2p[cb + ci])
                        + __ldg(&g_p2cT[pTb + (long long)pi * BS + t]);
                x *= inv;
                acc[f][rh * 2 + e] = x;
                rmax[rh] = fmaxf(rmax[rh], x);
            }
        }
    }
#pragma unroll
    for (int o = 1; o <= 2; o <<= 1) {
        rmax[0] = fmaxf(rmax[0], __shfl_xor_sync(0xffffffffu, rmax[0], o));
        rmax[1] = fmaxf(rmax[1], __shfl_xor_sync(0xffffffffu, rmax[1], o));
    }
    if (qt == 0) { red_m[sl0 * 8 + nw] = rmax[0]; red_m[(sl0 + 8) * 8 + nw] = rmax[1]; }
    __syncthreads();
    float mrow[2];
#pragma unroll
    for (int rh = 0; rh < 2; rh++) {
        float m = red_m[(sl0 + rh * 8) * 8];
#pragma unroll
        for (int j = 1; j < 8; j++) m = fmaxf(m, red_m[(sl0 + rh * 8) * 8 + j]);
        mrow[rh] = m;
    }
    float rsum[2] = {0.0f, 0.0f};
#pragma unroll
    for (int f = 0; f < 16; f++)
#pragma unroll
        for (int rh = 0; rh < 2; rh++)
#pragma unroll
            for (int e = 0; e < 2; e++) {
                float v = expf(acc[f][rh * 2 + e] - mrow[rh]);
                acc[f][rh * 2 + e] = v;
                rsum[rh] += v;
            }
#pragma unroll
    for (int o = 1; o <= 2; o <<= 1) {
        rsum[0] += __shfl_xor_sync(0xffffffffu, rsum[0], o);
        rsum[1] += __shfl_xor_sync(0xffffffffu, rsum[1], o);
    }
    if (qt == 0) { red_s[sl0 * 8 + nw] = rsum[0]; red_s[(sl0 + 8) * 8 + nw] = rsum[1]; }
    __syncthreads();
    float rinv[2];
#pragma unroll
    for (int rh = 0; rh < 2; rh++) {
        float sum = 0.0f;
#pragma unroll
        for (int j = 0; j < 8; j++) sum += red_s[(sl0 + rh * 8) * 8 + j];
        rinv[rh] = 1.0f / sum;
    }
#pragma unroll
    for (int rh = 0; rh < 2; rh++) {
        float* prow = probs + ((long long)bh * SEQ + s0 + sl0 + rh * 8) * SEQ;
#pragma unroll
        for (int f = 0; f < 16; f++) {
            int colb = f * 64 + wn + qt * 2;
            *reinterpret_cast<float2*>(&prow[colb]) =
                make_float2(acc[f][rh * 2] * rinv[rh], acc[f][rh * 2 + 1] * rinv[rh]);
        }
    }
}

// ctx = probs @ vT; A=probs needs cvt, B=v pre-rounded; output pre-rounded for k_out
__global__ void __launch_bounds__(256) k_ctx(const float* __restrict__ probs) {
    int z = blockIdx.y;
    int b = z / NH, h = z % NH;
    gemm_body<0, 64, true, false, true>(probs + (size_t)z * SEQ * SEQ, SEQ,
                     g_v + (size_t)z * D * SEQ, SEQ,
                     nullptr, nullptr, 0,
                     g_ctx + (size_t)(b * SEQ) * HID + h * D, HID, SEQ,
                     blockIdx.x * 64, 0);
}

__global__ void __launch_bounds__(256) k_out(const float* __restrict__ hs,
                                             const float* __restrict__ Wo, const float* __restrict__ bo) {
    gemm_body<2, 128, false, true, false>(g_ctx, HID, Wo, HID, bo, hs, HID, g_pre, HID, HID,
                      blockIdx.y * 128, blockIdx.x * 64);
}

// -------- layernorm over rows of g_pre --------
__global__ void ln_kernel(const float* __restrict__ lnw, const float* __restrict__ lnb,
                          float* __restrict__ out) {
    int row = blockIdx.x;
    const float* x = g_pre + (long long)row * HID;
    float* o = out + (long long)row * HID;
    int tid = threadIdx.x;
    __shared__ float red[8];
    float v[3];
    float s = 0.0f;
#pragma unroll
    for (int k = 0; k < 3; k++) {
        v[k] = x[tid + k * 256];
        s += v[k];
    }
#pragma unroll
    for (int o2 = 16; o2; o2 >>= 1) s += __shfl_xor_sync(0xffffffffu, s, o2);
    if ((tid & 31) == 0) red[tid >> 5] = s;
    __syncthreads();
    if (tid == 0) {
        float x2 = 0.0f;
#pragma unroll
        for (int i = 0; i < 8; i++) x2 += red[i];
        red[0] = x2;
    }
    __syncthreads();
    float mu = red[0] / (float)HID;
    __syncthreads();
    float sq = 0.0f;
#pragma unroll
    for (int k = 0; k < 3; k++) {
        float d = v[k] - mu;
        sq += d * d;
    }
#pragma unroll
    for (int o2 = 16; o2; o2 >>= 1) sq += __shfl_xor_sync(0xffffffffu, sq, o2);
    if ((tid & 31) == 0) red[tid >> 5] = sq;
    __syncthreads();
    if (tid == 0) {
        float x2 = 0.0f;
#pragma unroll
        for (int i = 0; i < 8; i++) x2 += red[i];
        red[0] = x2;
    }
    __syncthreads();
    float var = red[0] / (float)HID;
    float rstd = 1.0f / sqrtf(var + 1e-7f);
#pragma unroll
    for (int k = 0; k < 3; k++) {
        int c = tid + k * 256;
        o[c] = lnw[c] * (v[k] - mu) * rstd + lnb[c];
    }
}

extern "C" void kernel_launch(void* const* d_in, const int* in_sizes, int n_in,
                              void* d_out, int out_size) {
    const float* hs  = (const float*)d_in[0];
    const float* rel = (const float*)d_in[1];
    const float* Wq  = (const float*)d_in[2];
    const float* bq  = (const float*)d_in[3];
    const float* Wk  = (const float*)d_in[4];
    const float* bk  = (const float*)d_in[5];
    const float* Wv  = (const float*)d_in[6];
    const float* bv  = (const float*)d_in[7];
    const float* Wo  = (const float*)d_in[8];
    const float* bo  = (const float*)d_in[9];
    const float* lnw = (const float*)d_in[10];
    const float* lnb = (const float*)d_in[11];

    float* out   = (float*)d_out;
    float* probs = out + (size_t)BS * HID;

    const int GEMM128_SMEM = 4 * 192 * 20 * 4;   // 61440
    const int GEMM64_SMEM  = 4 * 128 * 20 * 4;   // 40960
    const int FUSED_SMEM = (32 * 68 + 4 * 64 * 68 + 512) * 4;  // 80384

    cudaFuncSetAttribute(k_proj,   cudaFuncAttributeMaxDynamicSharedMemorySize, GEMM128_SMEM);
    cudaFuncSetAttribute(k_posatt, cudaFuncAttributeMaxDynamicSharedMemorySize, GEMM128_SMEM);
    cudaFuncSetAttribute(k_out,    cudaFuncAttributeMaxDynamicSharedMemorySize, GEMM128_SMEM);
    cudaFuncSetAttribute(k_ctx,    cudaFuncAttributeMaxDynamicSharedMemorySize, GEMM64_SMEM);
    cudaFuncSetAttribute(k_fused_scores, cudaFuncAttributeMaxDynamicSharedMemorySize, FUSED_SMEM);

    relb_kernel<<<8, 256>>>();
    k_proj<<<dim3(HID / 64, 104), 256, GEMM128_SMEM>>>(hs, rel, Wq, bq, Wk, bk, Wv, bv);
    k_posatt<<<6144, 256, GEMM128_SMEM>>>();
    k_fused_scores<<<dim3(SEQ / 32, BAT * NH), 512, FUSED_SMEM>>>(probs);
    k_ctx<<<dim3(SEQ / 64, BAT * NH), 256, GEMM64_SMEM>>>(probs);
    k_out<<<dim3(HID / 64, BS / 128), 256, GEMM128_SMEM>>>(hs, Wo, bo);
    ln_kernel<<<BS, 256>>>(lnw, lnb, out);
}

// round 10
// speedup vs baseline: 1.1553x; 1.0028x over previous
#include <cuda_runtime.h>
#include <cuda_fp16.h>
#include <math.h>

#define NH   12
#define D    64
#define SEQ  1024
#define BAT  4
#define HID  768
#define BS   4096      // BAT*SEQ
#define POS  512       // 2*span
#define SPAN 256

// -------- scratch (static device memory; no allocations) --------
__device__ float  g_q[BS * HID];                   // tf32-rounded
__device__ float  g_k[BS * HID];                   // tf32-rounded
__device__ float  g_v[BS * HID];                   // tf32-rounded, [b][h][d][s]
__device__ float  g_ctx[BS * HID];                 // tf32-rounded
__device__ float  g_pre[BS * HID];
__device__ float  g_posk[POS * HID];               // tf32-rounded
__device__ float  g_posq[POS * HID];               // tf32-rounded
__device__ __half g_c2p[(size_t)NH * BS * POS];    // [h][b*S+s][512] fp16
__device__ __half g_p2cT[(size_t)NH * POS * BS];   // [h][bucket][b*S+t] fp16
__device__ int    g_c2pidx[2048];
__device__ int    g_p2cidx[2048];

// -------- relative-position bucket table (matches numpy exactly) --------
__global__ void relb_kernel() {
    int i = blockIdx.x * blockDim.x + threadIdx.x;
    if (i >= 2047) return;
    int rel = i - 1023;
    const int mid = 128;
    int sgn = (rel > 0) - (rel < 0);
    float abs_pos = (rel < mid && rel > -mid) ? (float)(mid - 1) : (float)abs(rel);
    float num32 = logf(abs_pos / 128.0f);
    double log_pos = ceil((double)num32 / log(511.0 / 128.0) * 127.0) + 128.0;
    long long bucket = (abs_pos <= 128.0f) ? (long long)rel
                                           : (long long)(log_pos * (double)sgn);
    int bi = (int)bucket;
    int c = bi + SPAN;  c = c < 0 ? 0 : (c > 2 * SPAN - 1 ? 2 * SPAN - 1 : c);
    int p = -bi + SPAN; p = p < 0 ? 0 : (p > 2 * SPAN - 1 ? 2 * SPAN - 1 : p);
    g_c2pidx[i] = c;
    g_p2cidx[i] = p;
}

// -------- tf32 helpers --------
__device__ __forceinline__ float f2tf(float x) {
    unsigned u;
    asm("cvt.rna.tf32.f32 %0, %1;" : "=r"(u) : "f"(x));
    return __uint_as_float(u);
}
__device__ __forceinline__ unsigned f2tfu(float x) {
    unsigned u;
    asm("cvt.rna.tf32.f32 %0, %1;" : "=r"(u) : "f"(x));
    return u;
}

__device__ __forceinline__ void mma_tf32(float* c, const unsigned* a, const unsigned* b) {
    asm volatile(
        "mma.sync.aligned.m16n8k8.row.col.f32.tf32.tf32.f32 "
        "{%0,%1,%2,%3},{%4,%5,%6,%7},{%8,%9},{%0,%1,%2,%3};"
        : "+f"(c[0]), "+f"(c[1]), "+f"(c[2]), "+f"(c[3])
        : "r"(a[0]), "r"(a[1]), "r"(a[2]), "r"(a[3]), "r"(b[0]), "r"(b[1]));
}

__device__ __forceinline__ void cp_async16(unsigned dst, const void* src) {
    asm volatile("cp.async.cg.shared.global [%0], [%1], 16;\n" :: "r"(dst), "l"(src));
}

// ======== generic NT GEMM with 4-stage cp.async ring ========
// C[TM x 64] tile of C = A[M,K] @ B[N,K]^T. 256 threads. BK=16.
// CVTA/CVTB: tf32 cvt at fragment load. RND: round fp32 outputs to tf32.
// OutT: float or __half. EPI: 0 plain, 1 +bias, 2 +bias+resid, 3 +bias, scatter vT
template<int EPI, int TM, bool CVTA, bool CVTB, bool RND, typename OutT>
__device__ __forceinline__ void gemm_body(
    const float* __restrict__ A, int lda,
    const float* __restrict__ B, int ldb,
    const float* __restrict__ bias,
    const float* __restrict__ resid, int ldr,
    OutT* __restrict__ C, long long ldc, int K,
    int row0, int col0)
{
    constexpr int MI = TM / 64;
    constexpr int ROWS = TM + 64;
    constexpr int CP = ROWS / 64;
    extern __shared__ float S[];             // [4][ROWS][20]
    int tid = threadIdx.x;
    int wid = tid >> 5, lane = tid & 31;
    int quad = lane >> 2, qt = lane & 3;
    int wm, wn;
    if (TM == 128) { wm = (wid >> 1) * 32; wn = (wid & 1) * 32; }
    else           { wm = (wid & 3) * 16;  wn = (wid >> 2) * 32; }

    const float* gsrc[CP];
    unsigned soff[CP];
    unsigned sbase = (unsigned)__cvta_generic_to_shared(S);
#pragma unroll
    for (int j = 0; j < CP; j++) {
        int lin = tid + j * 256;
        int row = lin >> 2, c4 = (lin & 3) * 4;
        soff[j] = row * 20 + c4;
        gsrc[j] = (row < TM) ? A + (long long)(row0 + row) * lda + c4
                             : B + (long long)(col0 + row - TM) * ldb + c4;
    }
    auto issue = [&](int cc) {
        int slot = cc & 3;
        long long k0 = (long long)cc * 16;
#pragma unroll
        for (int j = 0; j < CP; j++)
            cp_async16(sbase + (slot * ROWS * 20 + soff[j]) * 4, gsrc[j] + k0);
        asm volatile("cp.async.commit_group;\n");
    };

    float acc[MI][4][4];
#pragma unroll
    for (int i = 0; i < MI; i++)
#pragma unroll
        for (int j = 0; j < 4; j++)
#pragma unroll
            for (int l = 0; l < 4; l++) acc[i][j][l] = 0.0f;

    auto ldA = [&](const float* p) -> unsigned {
        return CVTA ? f2tfu(*p) : __float_as_uint(*p);
    };
    auto ldB = [&](const float* p) -> unsigned {
        return CVTB ? f2tfu(*p) : __float_as_uint(*p);
    };

    auto comp = [&](int slot) {
        const float* Sb = S + slot * ROWS * 20;
#pragma unroll
        for (int kk = 0; kk < 16; kk += 8) {
            unsigned af[MI][4], bfr[4][2];
#pragma unroll
            for (int mi = 0; mi < MI; mi++) {
                int r = wm + mi * 16 + quad;
                af[mi][0] = ldA(&Sb[r * 20 + kk + qt]);
                af[mi][1] = ldA(&Sb[(r + 8) * 20 + kk + qt]);
                af[mi][2] = ldA(&Sb[r * 20 + kk + qt + 4]);
                af[mi][3] = ldA(&Sb[(r + 8) * 20 + kk + qt + 4]);
            }
#pragma unroll
            for (int ni = 0; ni < 4; ni++) {
                int n = TM + wn + ni * 8 + quad;
                bfr[ni][0] = ldB(&Sb[n * 20 + kk + qt]);
                bfr[ni][1] = ldB(&Sb[n * 20 + kk + qt + 4]);
            }
#pragma unroll
            for (int mi = 0; mi < MI; mi++)
#pragma unroll
                for (int ni = 0; ni < 4; ni++)
                    mma_tf32(acc[mi][ni], af[mi], bfr[ni]);
        }
    };

    int nst = K >> 4;
    issue(0); issue(1); issue(2);
    for (int c = 0; c < nst; c++) {
        asm volatile("cp.async.wait_group %0;\n" :: "n"(2));
        __syncthreads();
        if (c + 3 < nst) issue(c + 3);
        else asm volatile("cp.async.commit_group;\n");
        comp(c & 3);
    }

    // epilogue
#pragma unroll
    for (int mi = 0; mi < MI; mi++) {
#pragma unroll
        for (int half = 0; half < 2; half++) {
            long long row = row0 + wm + mi * 16 + quad + half * 8;
#pragma unroll
            for (int ni = 0; ni < 4; ni++) {
                long long col = col0 + wn + ni * 8 + qt * 2;
                float v0 = acc[mi][ni][half * 2 + 0];
                float v1 = acc[mi][ni][half * 2 + 1];
                if (EPI >= 1) { v0 += bias[col]; v1 += bias[col + 1]; }
                if (EPI == 2) {
                    v0 += resid[row * ldr + col];
                    v1 += resid[row * ldr + col + 1];
                }
                if (RND) { v0 = f2tf(v0); v1 = f2tf(v1); }
                if (EPI == 3) {
                    int bb = (int)(row >> 10), ss = (int)(row & 1023);
                    int hh = (int)(col >> 6), dd = (int)(col & 63);
                    ((float*)C)[((((long long)bb * NH + hh) * D + dd) << 10) + ss] = v0;
                    hh = (int)((col + 1) >> 6); dd = (int)((col + 1) & 63);
                    ((float*)C)[((((long long)bb * NH + hh) * D + dd) << 10) + ss] = v1;
                } else if (sizeof(OutT) == 2) {
                    *reinterpret_cast<__half2*>((__half*)C + row * ldc + col) =
                        __floats2half2_rn(v0, v1);
                } else {
                    *reinterpret_cast<float2*>((float*)C + row * ldc + col) =
                        make_float2(v0, v1);
                }
            }
        }
    }
}

// -------- merged projection kernel: outputs tf32-pre-rounded --------
__global__ void __launch_bounds__(256) k_proj(
    const float* __restrict__ hs, const float* __restrict__ rel,
    const float* __restrict__ Wq, const float* __restrict__ bq,
    const float* __restrict__ Wk, const float* __restrict__ bk,
    const float* __restrict__ Wv, const float* __restrict__ bv)
{
    int y = blockIdx.y;
    int col0 = blockIdx.x * 64;
    if (y < 32)
        gemm_body<1, 128, true, true, true>(hs, HID, Wq, HID, bq, nullptr, 0, g_q, HID, HID, y * 128, col0);
    else if (y < 64)
        gemm_body<1, 128, true, true, true>(hs, HID, Wk, HID, bk, nullptr, 0, g_k, HID, HID, (y - 32) * 128, col0);
    else if (y < 96)
        gemm_body<3, 128, true, true, true>(hs, HID, Wv, HID, bv, nullptr, 0, g_v, HID, HID, (y - 64) * 128, col0);
    else if (y < 100)
        gemm_body<1, 128, true, true, true>(rel, HID, Wk, HID, bk, nullptr, 0, g_posk, HID, HID, (y - 96) * 128, col0);
    else
        gemm_body<1, 128, true, true, true>(rel, HID, Wq, HID, bq, nullptr, 0, g_posq, HID, HID, (y - 100) * 128, col0);
}

// -------- pos-att: c2p [h][s][bucket] and p2cT [h][bucket][t], fp16 outputs --------
__global__ void __launch_bounds__(256) k_posatt() {
    int z = blockIdx.x;
    if (z < 3072) {
        int h = z >> 8, r = z & 255;
        gemm_body<0, 128, false, false, false>(g_q + h * D, HID, g_posk + h * D, HID, nullptr, nullptr, 0,
                          g_c2p + (size_t)h * BS * POS, POS, D,
                          (r >> 3) * 128, (r & 7) * 64);
    } else {
        z -= 3072;
        int h = z >> 8, r = z & 255;
        gemm_body<0, 128, false, false, false>(g_posq + h * D, HID, g_k + h * D, HID, nullptr, nullptr, 0,
                          g_p2cT + (size_t)h * POS * BS, BS, D,
                          (r >> 6) * 128, (r & 63) * 64);
    }
}

// ======== FUSED scores + in-loop gathers + softmax -> probs ========
// 512 threads = 16 warps (2 m x 8 n). CTA tile: 32 rows x 1024 cols.
// acc[c] is FINAL after chunk c (K=64 per chunk) -> gathers fused per chunk,
// overlapping L2 latency with other warps' MMAs.
__global__ void __launch_bounds__(512, 1) k_fused_scores(float* __restrict__ probs) {
    extern __shared__ float dyn[];
    float* Qs    = dyn;                       // [32][68] (already tf32)
    float* Ks    = Qs + 32 * 68;              // [4][64][68] ring (already tf32)
    float* red_m = Ks + 4 * 64 * 68;          // [32][8]
    float* red_s = red_m + 256;               // [32][8]

    int s0 = blockIdx.x * 32;
    int bh = blockIdx.y;
    int b = bh / NH, h = bh % NH;
    int tid = threadIdx.x;
    int w = tid >> 5, lane = tid & 31;
    int quad = lane >> 2, qt = lane & 3;
    int wm = (w >> 3) * 16;
    int wn = (w & 7) * 8;
    int nw = w & 7;

    const float* kptr = g_k + ((long long)b * SEQ) * HID + h * D;
    unsigned ks_base = (unsigned)__cvta_generic_to_shared(Ks);

    int r0 = tid >> 4, c0 = (tid & 15) << 2;
    int r1 = (tid + 512) >> 4, c1 = ((tid + 512) & 15) << 2;

    auto issue_k = [&](int cc) {
        int slot = cc & 3;
        const float* srcb = kptr + (long long)cc * 64 * HID;
        cp_async16(ks_base + (unsigned)(((slot * 64 + r0) * 68 + c0) * 4),
                   srcb + (long long)r0 * HID + c0);
        cp_async16(ks_base + (unsigned)(((slot * 64 + r1) * 68 + c1) * 4),
                   srcb + (long long)r1 * HID + c1);
        asm volatile("cp.async.commit_group;\n");
    };

    issue_k(0); issue_k(1); issue_k(2);

    // q tile (32x64) — already tf32-rounded, stage raw
    {
        int m = tid >> 4, kq = (tid & 15) * 4;
        *reinterpret_cast<float4*>(&Qs[m * 68 + kq]) =
            *reinterpret_cast<const float4*>(
                g_q + ((long long)(b * SEQ + s0 + m)) * HID + h * D + kq);
    }
    __syncthreads();

    // hoist q fragments: 8 k-steps x 4 regs
    unsigned areg[8][4];
#pragma unroll
    for (int ks = 0; ks < 8; ks++) {
        int kk = ks * 8;
        areg[ks][0] = __float_as_uint(Qs[(wm + quad) * 68 + kk + qt]);
        areg[ks][1] = __float_as_uint(Qs[(wm + quad + 8) * 68 + kk + qt]);
        areg[ks][2] = __float_as_uint(Qs[(wm + quad) * 68 + kk + qt + 4]);
        areg[ks][3] = __float_as_uint(Qs[(wm + quad + 8) * 68 + kk + qt + 4]);
    }

    float acc[16][4];
#pragma unroll
    for (int f = 0; f < 16; f++)
#pragma unroll
        for (int j = 0; j < 4; j++) acc[f][j] = 0.0f;

    const float inv = rsqrtf(192.0f);
    int sl0 = wm + quad;
    long long c2pb0 = ((long long)h * BS + b * SEQ + s0 + sl0) * POS;
    long long c2pb1 = c2pb0 + 8LL * POS;
    long long pTb = (long long)h * POS * BS + (long long)b * SEQ;
    float rmax[2] = {-1e30f, -1e30f};

#pragma unroll
    for (int c = 0; c < 16; c++) {
        asm volatile("cp.async.wait_group %0;\n" :: "n"(2));
        __syncthreads();
        if (c < 13) issue_k(c + 3);
        else        asm volatile("cp.async.commit_group;\n");
        int slot = c & 3;
        const float* kb = &Ks[(slot * 64 + wn + quad) * 68];
#pragma unroll
        for (int ks = 0; ks < 8; ks++) {
            unsigned bb[2];
            bb[0] = __float_as_uint(kb[ks * 8 + qt]);
            bb[1] = __float_as_uint(kb[ks * 8 + qt + 4]);
            mma_tf32(acc[c], areg[ks], bb);
        }
        // fused rel-pos gathers for this (now final) chunk
        int colb = c * 64 + wn + qt * 2;
#pragma unroll
        for (int rh = 0; rh < 2; rh++) {
            int s = s0 + sl0 + rh * 8;
            long long cb = rh ? c2pb1 : c2pb0;
#pragma unroll
            for (int e = 0; e < 2; e++) {
                int t = colb + e;
                int dlt = s - t + 1023;
                int ci = __ldg(&g_c2pidx[dlt]);
                int pi = __ldg(&g_p2cidx[2046 - dlt]);
                float x = acc[c][rh * 2 + e]
                        + __half2float(__ldg(&g_c2p[cb + ci]))
                        + __half2float(__ldg(&g_p2cT[pTb + (long long)pi * BS + t]));
                x *= inv;
                acc[c][rh * 2 + e] = x;
                rmax[rh] = fmaxf(rmax[rh], x);
            }
        }
    }

    // ---- softmax reductions ----
#pragma unroll
    for (int o = 1; o <= 2; o <<= 1) {
        rmax[0] = fmaxf(rmax[0], __shfl_xor_sync(0xffffffffu, rmax[0], o));
        rmax[1] = fmaxf(rmax[1], __shfl_xor_sync(0xffffffffu, rmax[1], o));
    }
    if (qt == 0) { red_m[sl0 * 8 + nw] = rmax[0]; red_m[(sl0 + 8) * 8 + nw] = rmax[1]; }
    __syncthreads();
    float mrow[2];
#pragma unroll
    for (int rh = 0; rh < 2; rh++) {
        float m = red_m[(sl0 + rh * 8) * 8];
#pragma unroll
        for (int j = 1; j < 8; j++) m = fmaxf(m, red_m[(sl0 + rh * 8) * 8 + j]);
        mrow[rh] = m;
    }
    float rsum[2] = {0.0f, 0.0f};
#pragma unroll
    for (int f = 0; f < 16; f++)
#pragma unroll
        for (int rh = 0; rh < 2; rh++)
#pragma unroll
            for (int e = 0; e < 2; e++) {
                float v = __expf(acc[f][rh * 2 + e] - mrow[rh]);
                acc[f][rh * 2 + e] = v;
                rsum[rh] += v;
            }
#pragma unroll
    for (int o = 1; o <= 2; o <<= 1) {
        rsum[0] += __shfl_xor_sync(0xffffffffu, rsum[0], o);
        rsum[1] += __shfl_xor_sync(0xffffffffu, rsum[1], o);
    }
    if (qt == 0) { red_s[sl0 * 8 + nw] = rsum[0]; red_s[(sl0 + 8) * 8 + nw] = rsum[1]; }
    __syncthreads();
    float rinv[2];
#pragma unroll
    for (int rh = 0; rh < 2; rh++) {
        float sum = 0.0f;
#pragma unroll
        for (int j = 0; j < 8; j++) sum += red_s[(sl0 + rh * 8) * 8 + j];
        rinv[rh] = 1.0f / sum;
    }
#pragma unroll
    for (int rh = 0; rh < 2; rh++) {
        float* prow = probs + ((long long)bh * SEQ + s0 + sl0 + rh * 8) * SEQ;
#pragma unroll
        for (int f = 0; f < 16; f++) {
            int colb = f * 64 + wn + qt * 2;
            *reinterpret_cast<float2*>(&prow[colb]) =
                make_float2(acc[f][rh * 2] * rinv[rh], acc[f][rh * 2 + 1] * rinv[rh]);
        }
    }
}

// ctx = probs @ vT; A=probs needs cvt, B=v pre-rounded; output pre-rounded for k_out
__global__ void __launch_bounds__(256) k_ctx(const float* __restrict__ probs) {
    int z = blockIdx.y;
    int b = z / NH, h = z % NH;
    gemm_body<0, 64, true, false, true>(probs + (size_t)z * SEQ * SEQ, SEQ,
                     g_v + (size_t)z * D * SEQ, SEQ,
                     nullptr, nullptr, 0,
                     g_ctx + (size_t)(b * SEQ) * HID + h * D, HID, SEQ,
                     blockIdx.x * 64, 0);
}

__global__ void __launch_bounds__(256) k_out(const float* __restrict__ hs,
                                             const float* __restrict__ Wo, const float* __restrict__ bo) {
    gemm_body<2, 128, false, true, false>(g_ctx, HID, Wo, HID, bo, hs, HID, g_pre, HID, HID,
                      blockIdx.y * 128, blockIdx.x * 64);
}

// -------- layernorm over rows of g_pre --------
__global__ void ln_kernel(const float* __restrict__ lnw, const float* __restrict__ lnb,
                          float* __restrict__ out) {
    int row = blockIdx.x;
    const float* x = g_pre + (long long)row * HID;
    float* o = out + (long long)row * HID;
    int tid = threadIdx.x;
    __shared__ float red[8];
    float v[3];
    float s = 0.0f;
#pragma unroll
    for (int k = 0; k < 3; k++) {
        v[k] = x[tid + k * 256];
        s += v[k];
    }
#pragma unroll
    for (int o2 = 16; o2; o2 >>= 1) s += __shfl_xor_sync(0xffffffffu, s, o2);
    if ((tid & 31) == 0) red[tid >> 5] = s;
    __syncthreads();
    if (tid == 0) {
        float x2 = 0.0f;
#pragma unroll
        for (int i = 0; i < 8; i++) x2 += red[i];
        red[0] = x2;
    }
    __syncthreads();
    float mu = red[0] / (float)HID;
    __syncthreads();
    float sq = 0.0f;
#pragma unroll
    for (int k = 0; k < 3; k++) {
        float d = v[k] - mu;
        sq += d * d;
    }
#pragma unroll
    for (int o2 = 16; o2; o2 >>= 1) sq += __shfl_xor_sync(0xffffffffu, sq, o2);
    if ((tid & 31) == 0) red[tid >> 5] = sq;
    __syncthreads();
    if (tid == 0) {
        float x2 = 0.0f;
#pragma unroll
        for (int i = 0; i < 8; i++) x2 += red[i];
        red[0] = x2;
    }
    __syncthreads();
    float var = red[0] / (float)HID;
    float rstd = 1.0f / sqrtf(var + 1e-7f);
#pragma unroll
    for (int k = 0; k < 3; k++) {
        int c = tid + k * 256;
        o[c] = lnw[c] * (v[k] - mu) * rstd + lnb[c];
    }
}

extern "C" void kernel_launch(void* const* d_in, const int* in_sizes, int n_in,
                              void* d_out, int out_size) {
    const float* hs  = (const float*)d_in[0];
    const float* rel = (const float*)d_in[1];
    const float* Wq  = (const float*)d_in[2];
    const float* bq  = (const float*)d_in[3];
    const float* Wk  = (const float*)d_in[4];
    const float* bk  = (const float*)d_in[5];
    const float* Wv  = (const float*)d_in[6];
    const float* bv  = (const float*)d_in[7];
    const float* Wo  = (const float*)d_in[8];
    const float* bo  = (const float*)d_in[9];
    const float* lnw = (const float*)d_in[10];
    const float* lnb = (const float*)d_in[11];

    float* out   = (float*)d_out;
    float* probs = out + (size_t)BS * HID;

    const int GEMM128_SMEM = 4 * 192 * 20 * 4;   // 61440
    const int GEMM64_SMEM  = 4 * 128 * 20 * 4;   // 40960
    const int FUSED_SMEM = (32 * 68 + 4 * 64 * 68 + 512) * 4;  // 80384

    cudaFuncSetAttribute(k_proj,   cudaFuncAttributeMaxDynamicSharedMemorySize, GEMM128_SMEM);
    cudaFuncSetAttribute(k_posatt, cudaFuncAttributeMaxDynamicSharedMemorySize, GEMM128_SMEM);
    cudaFuncSetAttribute(k_out,    cudaFuncAttributeMaxDynamicSharedMemorySize, GEMM128_SMEM);
    cudaFuncSetAttribute(k_ctx,    cudaFuncAttributeMaxDynamicSharedMemorySize, GEMM64_SMEM);
    cudaFuncSetAttribute(k_fused_scores, cudaFuncAttributeMaxDynamicSharedMemorySize, FUSED_SMEM);

    relb_kernel<<<8, 256>>>();
    k_proj<<<dim3(HID / 64, 104), 256, GEMM128_SMEM>>>(hs, rel, Wq, bq, Wk, bk, Wv, bv);
    k_posatt<<<6144, 256, GEMM128_SMEM>>>();
    k_fused_scores<<<dim3(SEQ / 32, BAT * NH), 512, FUSED_SMEM>>>(probs);
    k_ctx<<<dim3(SEQ / 64, BAT * NH), 256, GEMM64_SMEM>>>(probs);
    k_out<<<dim3(HID / 64, BS / 128), 256, GEMM128_SMEM>>>(hs, Wo, bo);
    ln_kernel<<<BS, 256>>>(lnw, lnb, out);
}

// round 11
// speedup vs baseline: 1.2261x; 1.0613x over previous
#include <cuda_runtime.h>
#include <cuda_fp16.h>
#include <math.h>

#define NH   12
#define D    64
#define SEQ  1024
#define BAT  4
#define HID  768
#define BS   4096      // BAT*SEQ
#define POS  512       // 2*span
#define SPAN 256

// -------- scratch (static device memory; no allocations) --------
__device__ float  g_q[BS * HID];                   // tf32-rounded
__device__ float  g_k[BS * HID];                   // tf32-rounded
__device__ float  g_v[BS * HID];                   // tf32-rounded, [b][h][d][s]
__device__ float  g_ctx[BS * HID];                 // tf32-rounded
__device__ float  g_pre[BS * HID];
__device__ float  g_posk[POS * HID];               // tf32-rounded
__device__ float  g_posq[POS * HID];               // tf32-rounded
__device__ __half g_c2p[(size_t)NH * BS * POS];    // [h][b*S+s][512] fp16
__device__ __half g_p2cT[(size_t)NH * POS * BS];   // [h][bucket][b*S+t] fp16
__device__ int    g_c2pidx[2048];

// -------- relative-position bucket table (matches numpy exactly) --------
// NOTE: p2c's gather index equals c2p's: clip(-bucket(t-s)+span) == clip(bucket(s-t)+span)
// because the log-bucket map is odd-symmetric. One table serves both.
__global__ void relb_kernel() {
    int i = blockIdx.x * blockDim.x + threadIdx.x;
    if (i >= 2047) return;
    int rel = i - 1023;
    const int mid = 128;
    int sgn = (rel > 0) - (rel < 0);
    float abs_pos = (rel < mid && rel > -mid) ? (float)(mid - 1) : (float)abs(rel);
    float num32 = logf(abs_pos / 128.0f);
    double log_pos = ceil((double)num32 / log(511.0 / 128.0) * 127.0) + 128.0;
    long long bucket = (abs_pos <= 128.0f) ? (long long)rel
                                           : (long long)(log_pos * (double)sgn);
    int bi = (int)bucket;
    int c = bi + SPAN;  c = c < 0 ? 0 : (c > 2 * SPAN - 1 ? 2 * SPAN - 1 : c);
    g_c2pidx[i] = c;
}

// -------- tf32 helpers --------
__device__ __forceinline__ float f2tf(float x) {
    unsigned u;
    asm("cvt.rna.tf32.f32 %0, %1;" : "=r"(u) : "f"(x));
    return __uint_as_float(u);
}
__device__ __forceinline__ unsigned f2tfu(float x) {
    unsigned u;
    asm("cvt.rna.tf32.f32 %0, %1;" : "=r"(u) : "f"(x));
    return u;
}

__device__ __forceinline__ void mma_tf32(float* c, const unsigned* a, const unsigned* b) {
    asm volatile(
        "mma.sync.aligned.m16n8k8.row.col.f32.tf32.tf32.f32 "
        "{%0,%1,%2,%3},{%4,%5,%6,%7},{%8,%9},{%0,%1,%2,%3};"
        : "+f"(c[0]), "+f"(c[1]), "+f"(c[2]), "+f"(c[3])
        : "r"(a[0]), "r"(a[1]), "r"(a[2]), "r"(a[3]), "r"(b[0]), "r"(b[1]));
}

__device__ __forceinline__ void cp_async16(unsigned dst, const void* src) {
    asm volatile("cp.async.cg.shared.global [%0], [%1], 16;\n" :: "r"(dst), "l"(src));
}

// ======== generic NT GEMM with 4-stage cp.async ring ========
// C[TM x TN] tile (TM=128; TN 64 or 128). 256 threads. BK=16.
// CVTA/CVTB: tf32 cvt at fragment load. RND: round fp32 outputs to tf32.
// OutT: float or __half. EPI: 0 plain, 1 +bias, 2 +bias+resid, 3 +bias, scatter vT
template<int EPI, int TM, int TN, bool CVTA, bool CVTB, bool RND, typename OutT>
__device__ __forceinline__ void gemm_body(
    const float* __restrict__ A, int lda,
    const float* __restrict__ B, int ldb,
    const float* __restrict__ bias,
    const float* __restrict__ resid, int ldr,
    OutT* __restrict__ C, long long ldc, int K,
    int row0, int col0)
{
    constexpr int MI = 2;                 // warp covers 32 rows
    constexpr int NI = (TN == 64) ? 4 : 8; // warp covers 32 or 64 cols
    constexpr int ROWS = TM + TN;
    constexpr int CP = ROWS / 64;
    extern __shared__ float S[];          // [4][ROWS][20]
    int tid = threadIdx.x;
    int wid = tid >> 5, lane = tid & 31;
    int quad = lane >> 2, qt = lane & 3;
    int wm, wn;
    if (TN == 64) { wm = (wid >> 1) * 32; wn = (wid & 1) * 32; }
    else          { wm = (wid & 3) * 32;  wn = (wid >> 2) * 64; }

    const float* gsrc[CP];
    unsigned soff[CP];
    unsigned sbase = (unsigned)__cvta_generic_to_shared(S);
#pragma unroll
    for (int j = 0; j < CP; j++) {
        int lin = tid + j * 256;
        int row = lin >> 2, c4 = (lin & 3) * 4;
        soff[j] = row * 20 + c4;
        gsrc[j] = (row < TM) ? A + (long long)(row0 + row) * lda + c4
                             : B + (long long)(col0 + row - TM) * ldb + c4;
    }
    auto issue = [&](int cc) {
        int slot = cc & 3;
        long long k0 = (long long)cc * 16;
#pragma unroll
        for (int j = 0; j < CP; j++)
            cp_async16(sbase + (slot * ROWS * 20 + soff[j]) * 4, gsrc[j] + k0);
        asm volatile("cp.async.commit_group;\n");
    };

    float acc[MI][NI][4];
#pragma unroll
    for (int i = 0; i < MI; i++)
#pragma unroll
        for (int j = 0; j < NI; j++)
#pragma unroll
            for (int l = 0; l < 4; l++) acc[i][j][l] = 0.0f;

    auto ldA = [&](const float* p) -> unsigned {
        return CVTA ? f2tfu(*p) : __float_as_uint(*p);
    };
    auto ldB = [&](const float* p) -> unsigned {
        return CVTB ? f2tfu(*p) : __float_as_uint(*p);
    };

    auto comp = [&](int slot) {
        const float* Sb = S + slot * ROWS * 20;
#pragma unroll
        for (int kk = 0; kk < 16; kk += 8) {
            unsigned af[MI][4], bfr[NI][2];
#pragma unroll
            for (int mi = 0; mi < MI; mi++) {
                int r = wm + mi * 16 + quad;
                af[mi][0] = ldA(&Sb[r * 20 + kk + qt]);
                af[mi][1] = ldA(&Sb[(r + 8) * 20 + kk + qt]);
                af[mi][2] = ldA(&Sb[r * 20 + kk + qt + 4]);
                af[mi][3] = ldA(&Sb[(r + 8) * 20 + kk + qt + 4]);
            }
#pragma unroll
            for (int ni = 0; ni < NI; ni++) {
                int n = TM + wn + ni * 8 + quad;
                bfr[ni][0] = ldB(&Sb[n * 20 + kk + qt]);
                bfr[ni][1] = ldB(&Sb[n * 20 + kk + qt + 4]);
            }
#pragma unroll
            for (int mi = 0; mi < MI; mi++)
#pragma unroll
                for (int ni = 0; ni < NI; ni++)
                    mma_tf32(acc[mi][ni], af[mi], bfr[ni]);
        }
    };

    int nst = K >> 4;
    issue(0); issue(1); issue(2);
    for (int c = 0; c < nst; c++) {
        asm volatile("cp.async.wait_group %0;\n" :: "n"(2));
        __syncthreads();
        if (c + 3 < nst) issue(c + 3);
        else asm volatile("cp.async.commit_group;\n");
        comp(c & 3);
    }

    // epilogue
#pragma unroll
    for (int mi = 0; mi < MI; mi++) {
#pragma unroll
        for (int half = 0; half < 2; half++) {
            long long row = row0 + wm + mi * 16 + quad + half * 8;
#pragma unroll
            for (int ni = 0; ni < NI; ni++) {
                long long col = col0 + wn + ni * 8 + qt * 2;
                float v0 = acc[mi][ni][half * 2 + 0];
                float v1 = acc[mi][ni][half * 2 + 1];
                if (EPI >= 1) { v0 += bias[col]; v1 += bias[col + 1]; }
                if (EPI == 2) {
                    v0 += resid[row * ldr + col];
                    v1 += resid[row * ldr + col + 1];
                }
                if (RND) { v0 = f2tf(v0); v1 = f2tf(v1); }
                if (EPI == 3) {
                    int bb = (int)(row >> 10), ss = (int)(row & 1023);
                    int hh = (int)(col >> 6), dd = (int)(col & 63);
                    ((float*)C)[((((long long)bb * NH + hh) * D + dd) << 10) + ss] = v0;
                    hh = (int)((col + 1) >> 6); dd = (int)((col + 1) & 63);
                    ((float*)C)[((((long long)bb * NH + hh) * D + dd) << 10) + ss] = v1;
                } else if (sizeof(OutT) == 2) {
                    *reinterpret_cast<__half2*>((__half*)C + row * ldc + col) =
                        __floats2half2_rn(v0, v1);
                } else {
                    *reinterpret_cast<float2*>((float*)C + row * ldc + col) =
                        make_float2(v0, v1);
                }
            }
        }
    }
}

// -------- merged projection kernel: 128x128 tiles, tf32-pre-rounded outputs --------
__global__ void __launch_bounds__(256) k_proj(
    const float* __restrict__ hs, const float* __restrict__ rel,
    const float* __restrict__ Wq, const float* __restrict__ bq,
    const float* __restrict__ Wk, const float* __restrict__ bk,
    const float* __restrict__ Wv, const float* __restrict__ bv)
{
    int y = blockIdx.y;
    int col0 = blockIdx.x * 128;
    if (y < 32)
        gemm_body<1, 128, 128, true, true, true>(hs, HID, Wq, HID, bq, nullptr, 0, g_q, HID, HID, y * 128, col0);
    else if (y < 64)
        gemm_body<1, 128, 128, true, true, true>(hs, HID, Wk, HID, bk, nullptr, 0, g_k, HID, HID, (y - 32) * 128, col0);
    else if (y < 96)
        gemm_body<3, 128, 128, true, true, true>(hs, HID, Wv, HID, bv, nullptr, 0, g_v, HID, HID, (y - 64) * 128, col0);
    else if (y < 100)
        gemm_body<1, 128, 128, true, true, true>(rel, HID, Wk, HID, bk, nullptr, 0, g_posk, HID, HID, (y - 96) * 128, col0);
    else
        gemm_body<1, 128, 128, true, true, true>(rel, HID, Wq, HID, bq, nullptr, 0, g_posq, HID, HID, (y - 100) * 128, col0);
}

// -------- pos-att: c2p [h][s][bucket] and p2cT [h][bucket][t], fp16, 128x128 tiles --------
__global__ void __launch_bounds__(256) k_posatt() {
    int z = blockIdx.x;
    if (z < 1536) {                               // c2p: M=4096, N=512 per head
        int h = z >> 7, r = z & 127;
        gemm_body<0, 128, 128, false, false, false>(g_q + h * D, HID, g_posk + h * D, HID, nullptr, nullptr, 0,
                          g_c2p + (size_t)h * BS * POS, POS, D,
                          (r >> 2) * 128, (r & 3) * 128);
    } else {                                      // p2cT: M=512, N=4096 per head
        z -= 1536;
        int h = z >> 7, r = z & 127;
        gemm_body<0, 128, 128, false, false, false>(g_posq + h * D, HID, g_k + h * D, HID, nullptr, nullptr, 0,
                          g_p2cT + (size_t)h * POS * BS, BS, D,
                          (r >> 5) * 128, (r & 31) * 128);
    }
}

// ======== FUSED scores + in-loop gathers + softmax -> probs ========
// 512 threads = 16 warps (2 m x 8 n). CTA tile: 32 rows x 1024 cols.
// 6-slot cp.async ring, 2 chunks per barrier, single shared gather index (ci==pi).
__global__ void __launch_bounds__(512, 1) k_fused_scores(float* __restrict__ probs) {
    extern __shared__ float dyn[];
    float* Qs    = dyn;                       // [32][68] (already tf32)
    float* Ks    = Qs + 32 * 68;              // [6][64][68] ring (already tf32)
    float* red_m = Ks + 6 * 64 * 68;          // [32][8]
    float* red_s = red_m + 256;               // [32][8]

    int s0 = blockIdx.x * 32;
    int bh = blockIdx.y;
    int b = bh / NH, h = bh % NH;
    int tid = threadIdx.x;
    int w = tid >> 5, lane = tid & 31;
    int quad = lane >> 2, qt = lane & 3;
    int wm = (w >> 3) * 16;
    int wn = (w & 7) * 8;
    int nw = w & 7;

    const float* kptr = g_k + ((long long)b * SEQ) * HID + h * D;
    unsigned ks_base = (unsigned)__cvta_generic_to_shared(Ks);

    int r0 = tid >> 4, c0 = (tid & 15) << 2;
    int r1 = (tid + 512) >> 4, c1 = ((tid + 512) & 15) << 2;

    auto issue_k = [&](int cc) {
        int slot = cc % 6;
        const float* srcb = kptr + (long long)cc * 64 * HID;
        cp_async16(ks_base + (unsigned)(((slot * 64 + r0) * 68 + c0) * 4),
                   srcb + (long long)r0 * HID + c0);
        cp_async16(ks_base + (unsigned)(((slot * 64 + r1) * 68 + c1) * 4),
                   srcb + (long long)r1 * HID + c1);
        asm volatile("cp.async.commit_group;\n");
    };

    issue_k(0); issue_k(1); issue_k(2); issue_k(3);

    // q tile (32x64) — already tf32-rounded, stage raw
    {
        int m = tid >> 4, kq = (tid & 15) * 4;
        *reinterpret_cast<float4*>(&Qs[m * 68 + kq]) =
            *reinterpret_cast<const float4*>(
                g_q + ((long long)(b * SEQ + s0 + m)) * HID + h * D + kq);
    }
    __syncthreads();

    // hoist q fragments: 8 k-steps x 4 regs
    unsigned areg[8][4];
#pragma unroll
    for (int ks = 0; ks < 8; ks++) {
        int kk = ks * 8;
        areg[ks][0] = __float_as_uint(Qs[(wm + quad) * 68 + kk + qt]);
        areg[ks][1] = __float_as_uint(Qs[(wm + quad + 8) * 68 + kk + qt]);
        areg[ks][2] = __float_as_uint(Qs[(wm + quad) * 68 + kk + qt + 4]);
        areg[ks][3] = __float_as_uint(Qs[(wm + quad + 8) * 68 + kk + qt + 4]);
    }

    float acc[16][4];
#pragma unroll
    for (int f = 0; f < 16; f++)
#pragma unroll
        for (int j = 0; j < 4; j++) acc[f][j] = 0.0f;

    const float inv = rsqrtf(192.0f);
    int sl0 = wm + quad;
    long long c2pb0 = ((long long)h * BS + b * SEQ + s0 + sl0) * POS;
    long long c2pb1 = c2pb0 + 8LL * POS;
    long long pTb = (long long)h * POS * BS + (long long)b * SEQ;
    float rmax[2] = {-1e30f, -1e30f};

    auto do_chunk = [&](int c) {
        int slot = c % 6;
        const float* kb = &Ks[(slot * 64 + wn + quad) * 68];
#pragma unroll
        for (int ks = 0; ks < 8; ks++) {
            unsigned bb[2];
            bb[0] = __float_as_uint(kb[ks * 8 + qt]);
            bb[1] = __float_as_uint(kb[ks * 8 + qt + 4]);
            mma_tf32(acc[c], areg[ks], bb);
        }
        int colb = c * 64 + wn + qt * 2;
#pragma unroll
        for (int rh = 0; rh < 2; rh++) {
            int s = s0 + sl0 + rh * 8;
            long long cb = rh ? c2pb1 : c2pb0;
#pragma unroll
            for (int e = 0; e < 2; e++) {
                int t = colb + e;
                int ci = __ldg(&g_c2pidx[s - t + 1023]);   // == p2c index (odd symmetry)
                float x = acc[c][rh * 2 + e]
                        + __half2float(__ldg(&g_c2p[cb + ci]))
                        + __half2float(__ldg(&g_p2cT[pTb + (long long)ci * BS + t]));
                x *= inv;
                acc[c][rh * 2 + e] = x;
                rmax[rh] = fmaxf(rmax[rh], x);
            }
        }
    };

#pragma unroll
    for (int c = 0; c < 16; c += 2) {
        asm volatile("cp.async.wait_group %0;\n" :: "n"(2));
        __syncthreads();
        if (c + 4 < 16) issue_k(c + 4);
        else            asm volatile("cp.async.commit_group;\n");
        if (c + 5 < 16) issue_k(c + 5);
        else            asm volatile("cp.async.commit_group;\n");
        do_chunk(c);
        do_chunk(c + 1);
    }

    // ---- softmax reductions ----
#pragma unroll
    for (int o = 1; o <= 2; o <<= 1) {
        rmax[0] = fmaxf(rmax[0], __shfl_xor_sync(0xffffffffu, rmax[0], o));
        rmax[1] = fmaxf(rmax[1], __shfl_xor_sync(0xffffffffu, rmax[1], o));
    }
    if (qt == 0) { red_m[sl0 * 8 + nw] = rmax[0]; red_m[(sl0 + 8) * 8 + nw] = rmax[1]; }
    __syncthreads();
    float mrow[2];
#pragma unroll
    for (int rh = 0; rh < 2; rh++) {
        float m = red_m[(sl0 + rh * 8) * 8];
#pragma unroll
        for (int j = 1; j < 8; j++) m = fmaxf(m, red_m[(sl0 + rh * 8) * 8 + j]);
        mrow[rh] = m;
    }
    float rsum[2] = {0.0f, 0.0f};
#pragma unroll
    for (int f = 0; f < 16; f++)
#pragma unroll
        for (int rh = 0; rh < 2; rh++)
#pragma unroll
            for (int e = 0; e < 2; e++) {
                float v = __expf(acc[f][rh * 2 + e] - mrow[rh]);
                acc[f][rh * 2 + e] = v;
                rsum[rh] += v;
            }
#pragma unroll
    for (int o = 1; o <= 2; o <<= 1) {
        rsum[0] += __shfl_xor_sync(0xffffffffu, rsum[0], o);
        rsum[1] += __shfl_xor_sync(0xffffffffu, rsum[1], o);
    }
    if (qt == 0) { red_s[sl0 * 8 + nw] = rsum[0]; red_s[(sl0 + 8) * 8 + nw] = rsum[1]; }
    __syncthreads();
    float rinv[2];
#pragma unroll
    for (int rh = 0; rh < 2; rh++) {
        float sum = 0.0f;
#pragma unroll
        for (int j = 0; j < 8; j++) sum += red_s[(sl0 + rh * 8) * 8 + j];
        rinv[rh] = 1.0f / sum;
    }
#pragma unroll
    for (int rh = 0; rh < 2; rh++) {
        float* prow = probs + ((long long)bh * SEQ + s0 + sl0 + rh * 8) * SEQ;
#pragma unroll
        for (int f = 0; f < 16; f++) {
            int colb = f * 64 + wn + qt * 2;
            *reinterpret_cast<float2*>(&prow[colb]) =
                make_float2(acc[f][rh * 2] * rinv[rh], acc[f][rh * 2 + 1] * rinv[rh]);
        }
    }
}

// ctx = probs @ vT; A=probs needs cvt, B=v pre-rounded; output pre-rounded for k_out
__global__ void __launch_bounds__(256) k_ctx(const float* __restrict__ probs) {
    int z = blockIdx.y;
    int b = z / NH, h = z % NH;
    gemm_body<0, 128, 64, true, false, true>(probs + (size_t)z * SEQ * SEQ, SEQ,
                     g_v + (size_t)z * D * SEQ, SEQ,
                     nullptr, nullptr, 0,
                     g_ctx + (size_t)(b * SEQ) * HID + h * D, HID, SEQ,
                     blockIdx.x * 128, 0);
}

__global__ void __launch_bounds__(256) k_out(const float* __restrict__ hs,
                                             const float* __restrict__ Wo, const float* __restrict__ bo) {
    gemm_body<2, 128, 128, false, true, false>(g_ctx, HID, Wo, HID, bo, hs, HID, g_pre, HID, HID,
                      blockIdx.y * 128, blockIdx.x * 128);
}

// -------- layernorm over rows of g_pre --------
__global__ void ln_kernel(const float* __restrict__ lnw, const float* __restrict__ lnb,
                          float* __restrict__ out) {
    int row = blockIdx.x;
    const float* x = g_pre + (long long)row * HID;
    float* o = out + (long long)row * HID;
    int tid = threadIdx.x;
    __shared__ float red[8];
    float v[3];
    float s = 0.0f;
#pragma unroll
    for (int k = 0; k < 3; k++) {
        v[k] = x[tid + k * 256];
        s += v[k];
    }
#pragma unroll
    for (int o2 = 16; o2; o2 >>= 1) s += __shfl_xor_sync(0xffffffffu, s, o2);
    if ((tid & 31) == 0) red[tid >> 5] = s;
    __syncthreads();
    if (tid == 0) {
        float x2 = 0.0f;
#pragma unroll
        for (int i = 0; i < 8; i++) x2 += red[i];
        red[0] = x2;
    }
    __syncthreads();
    float mu = red[0] / (float)HID;
    __syncthreads();
    float sq = 0.0f;
#pragma unroll
    for (int k = 0; k < 3; k++) {
        float d = v[k] - mu;
        sq += d * d;
    }
#pragma unroll
    for (int o2 = 16; o2; o2 >>= 1) sq += __shfl_xor_sync(0xffffffffu, sq, o2);
    if ((tid & 31) == 0) red[tid >> 5] = sq;
    __syncthreads();
    if (tid == 0) {
        float x2 = 0.0f;
#pragma unroll
        for (int i = 0; i < 8; i++) x2 += red[i];
        red[0] = x2;
    }
    __syncthreads();
    float var = red[0] / (float)HID;
    float rstd = 1.0f / sqrtf(var + 1e-7f);
#pragma unroll
    for (int k = 0; k < 3; k++) {
        int c = tid + k * 256;
        o[c] = lnw[c] * (v[k] - mu) * rstd + lnb[c];
    }
}

extern "C" void kernel_launch(void* const* d_in, const int* in_sizes, int n_in,
                              void* d_out, int out_size) {
    const float* hs  = (const float*)d_in[0];
    const float* rel = (const float*)d_in[1];
    const float* Wq  = (const float*)d_in[2];
    const float* bq  = (const float*)d_in[3];
    const float* Wk  = (const float*)d_in[4];
    const float* bk  = (const float*)d_in[5];
    const float* Wv  = (const float*)d_in[6];
    const float* bv  = (const float*)d_in[7];
    const float* Wo  = (const float*)d_in[8];
    const float* bo  = (const float*)d_in[9];
    const float* lnw = (const float*)d_in[10];
    const float* lnb = (const float*)d_in[11];

    float* out   = (float*)d_out;
    float* probs = out + (size_t)BS * HID;

    const int GEMM_N128_SMEM = 4 * 256 * 20 * 4;  // 81920
    const int GEMM_N64_SMEM  = 4 * 192 * 20 * 4;  // 61440
    const int FUSED_SMEM = (32 * 68 + 6 * 64 * 68 + 512) * 4;  // 115200

    cudaFuncSetAttribute(k_proj,   cudaFuncAttributeMaxDynamicSharedMemorySize, GEMM_N128_SMEM);
    cudaFuncSetAttribute(k_posatt, cudaFuncAttributeMaxDynamicSharedMemorySize, GEMM_N128_SMEM);
    cudaFuncSetAttribute(k_out,    cudaFuncAttributeMaxDynamicSharedMemorySize, GEMM_N128_SMEM);
    cudaFuncSetAttribute(k_ctx,    cudaFuncAttributeMaxDynamicSharedMemorySize, GEMM_N64_SMEM);
    cudaFuncSetAttribute(k_fused_scores, cudaFuncAttributeMaxDynamicSharedMemorySize, FUSED_SMEM);

    relb_kernel<<<8, 256>>>();
    k_proj<<<dim3(HID / 128, 104), 256, GEMM_N128_SMEM>>>(hs, rel, Wq, bq, Wk, bk, Wv, bv);
    k_posatt<<<3072, 256, GEMM_N128_SMEM>>>();
    k_fused_scores<<<dim3(SEQ / 32, BAT * NH), 512, FUSED_SMEM>>>(probs);
    k_ctx<<<dim3(SEQ / 128, BAT * NH), 256, GEMM_N64_SMEM>>>(probs);
    k_out<<<dim3(HID / 128, BS / 128), 256, GEMM_N128_SMEM>>>(hs, Wo, bo);
    ln_kernel<<<BS, 256>>>(lnw, lnb, out);
}

// round 12
// speedup vs baseline: 1.2625x; 1.0296x over previous
#include <cuda_runtime.h>
#include <cuda_fp16.h>
#include <math.h>

#define NH   12
#define D    64
#define SEQ  1024
#define BAT  4
#define HID  768
#define BS   4096      // BAT*SEQ
#define POS  512       // 2*span
#define SPAN 256

// -------- scratch (static device memory; no allocations) --------
__device__ float  g_q[BS * HID];                   // tf32-rounded
__device__ float  g_k[BS * HID];                   // tf32-rounded
__device__ float  g_v[BS * HID];                   // tf32-rounded, [b][h][d][s]
__device__ float  g_ctx[BS * HID];                 // tf32-rounded
__device__ float  g_pre[BS * HID];
__device__ float  g_posk[POS * HID];               // tf32-rounded
__device__ float  g_posq[POS * HID];               // tf32-rounded
__device__ __half g_c2p[(size_t)NH * BS * POS];    // [h][b*S+s][512] fp16
__device__ __half g_p2cT[(size_t)NH * POS * BS];   // [h][bucket][b*S+t] fp16
__device__ int    g_c2pidx[2048];

// -------- relative-position bucket table (matches numpy exactly) --------
// p2c's gather index equals c2p's (log-bucket map is odd-symmetric); one table.
__global__ void relb_kernel() {
    int i = blockIdx.x * blockDim.x + threadIdx.x;
    if (i >= 2047) return;
    int rel = i - 1023;
    const int mid = 128;
    int sgn = (rel > 0) - (rel < 0);
    float abs_pos = (rel < mid && rel > -mid) ? (float)(mid - 1) : (float)abs(rel);
    float num32 = logf(abs_pos / 128.0f);
    double log_pos = ceil((double)num32 / log(511.0 / 128.0) * 127.0) + 128.0;
    long long bucket = (abs_pos <= 128.0f) ? (long long)rel
                                           : (long long)(log_pos * (double)sgn);
    int bi = (int)bucket;
    int c = bi + SPAN;  c = c < 0 ? 0 : (c > 2 * SPAN - 1 ? 2 * SPAN - 1 : c);
    g_c2pidx[i] = c;
}

// -------- tf32 helpers --------
__device__ __forceinline__ float f2tf(float x) {
    unsigned u;
    asm("cvt.rna.tf32.f32 %0, %1;" : "=r"(u) : "f"(x));
    return __uint_as_float(u);
}
__device__ __forceinline__ unsigned f2tfu(float x) {
    unsigned u;
    asm("cvt.rna.tf32.f32 %0, %1;" : "=r"(u) : "f"(x));
    return u;
}

__device__ __forceinline__ void mma_tf32(float* c, const unsigned* a, const unsigned* b) {
    asm volatile(
        "mma.sync.aligned.m16n8k8.row.col.f32.tf32.tf32.f32 "
        "{%0,%1,%2,%3},{%4,%5,%6,%7},{%8,%9},{%0,%1,%2,%3};"
        : "+f"(c[0]), "+f"(c[1]), "+f"(c[2]), "+f"(c[3])
        : "r"(a[0]), "r"(a[1]), "r"(a[2]), "r"(a[3]), "r"(b[0]), "r"(b[1]));
}

__device__ __forceinline__ void cp_async16(unsigned dst, const void* src) {
    asm volatile("cp.async.cg.shared.global [%0], [%1], 16;\n" :: "r"(dst), "l"(src));
}

// ======== generic NT GEMM with 4-stage cp.async ring ========
// C[TM x TN] tile (TM=128; TN 64 or 128). 256 threads. BK=16.
// CVTA/CVTB: tf32 cvt at fragment load. RND: round fp32 outputs to tf32.
// OutT: float or __half. EPI: 0 plain, 1 +bias, 2 +bias+resid, 3 +bias, scatter vT
template<int EPI, int TM, int TN, bool CVTA, bool CVTB, bool RND, typename OutT>
__device__ __forceinline__ void gemm_body(
    const float* __restrict__ A, int lda,
    const float* __restrict__ B, int ldb,
    const float* __restrict__ bias,
    const float* __restrict__ resid, int ldr,
    OutT* __restrict__ C, long long ldc, int K,
    int row0, int col0)
{
    constexpr int MI = 2;
    constexpr int NI = (TN == 64) ? 4 : 8;
    constexpr int ROWS = TM + TN;
    constexpr int CP = ROWS / 64;
    extern __shared__ float S[];          // [4][ROWS][20]
    int tid = threadIdx.x;
    int wid = tid >> 5, lane = tid & 31;
    int quad = lane >> 2, qt = lane & 3;
    int wm, wn;
    if (TN == 64) { wm = (wid >> 1) * 32; wn = (wid & 1) * 32; }
    else          { wm = (wid & 3) * 32;  wn = (wid >> 2) * 64; }

    const float* gsrc[CP];
    unsigned soff[CP];
    unsigned sbase = (unsigned)__cvta_generic_to_shared(S);
#pragma unroll
    for (int j = 0; j < CP; j++) {
        int lin = tid + j * 256;
        int row = lin >> 2, c4 = (lin & 3) * 4;
        soff[j] = row * 20 + c4;
        gsrc[j] = (row < TM) ? A + (long long)(row0 + row) * lda + c4
                             : B + (long long)(col0 + row - TM) * ldb + c4;
    }
    auto issue = [&](int cc) {
        int slot = cc & 3;
        long long k0 = (long long)cc * 16;
#pragma unroll
        for (int j = 0; j < CP; j++)
            cp_async16(sbase + (slot * ROWS * 20 + soff[j]) * 4, gsrc[j] + k0);
        asm volatile("cp.async.commit_group;\n");
    };

    float acc[MI][NI][4];
#pragma unroll
    for (int i = 0; i < MI; i++)
#pragma unroll
        for (int j = 0; j < NI; j++)
#pragma unroll
            for (int l = 0; l < 4; l++) acc[i][j][l] = 0.0f;

    auto ldA = [&](const float* p) -> unsigned {
        return CVTA ? f2tfu(*p) : __float_as_uint(*p);
    };
    auto ldB = [&](const float* p) -> unsigned {
        return CVTB ? f2tfu(*p) : __float_as_uint(*p);
    };

    auto comp = [&](int slot) {
        const float* Sb = S + slot * ROWS * 20;
#pragma unroll
        for (int kk = 0; kk < 16; kk += 8) {
            unsigned af[MI][4], bfr[NI][2];
#pragma unroll
            for (int mi = 0; mi < MI; mi++) {
                int r = wm + mi * 16 + quad;
                af[mi][0] = ldA(&Sb[r * 20 + kk + qt]);
                af[mi][1] = ldA(&Sb[(r + 8) * 20 + kk + qt]);
                af[mi][2] = ldA(&Sb[r * 20 + kk + qt + 4]);
                af[mi][3] = ldA(&Sb[(r + 8) * 20 + kk + qt + 4]);
            }
#pragma unroll
            for (int ni = 0; ni < NI; ni++) {
                int n = TM + wn + ni * 8 + quad;
                bfr[ni][0] = ldB(&Sb[n * 20 + kk + qt]);
                bfr[ni][1] = ldB(&Sb[n * 20 + kk + qt + 4]);
            }
#pragma unroll
            for (int mi = 0; mi < MI; mi++)
#pragma unroll
                for (int ni = 0; ni < NI; ni++)
                    mma_tf32(acc[mi][ni], af[mi], bfr[ni]);
        }
    };

    int nst = K >> 4;
    issue(0); issue(1); issue(2);
    for (int c = 0; c < nst; c++) {
        asm volatile("cp.async.wait_group %0;\n" :: "n"(2));
        __syncthreads();
        if (c + 3 < nst) issue(c + 3);
        else asm volatile("cp.async.commit_group;\n");
        comp(c & 3);
    }

    // epilogue
#pragma unroll
    for (int mi = 0; mi < MI; mi++) {
#pragma unroll
        for (int half = 0; half < 2; half++) {
            long long row = row0 + wm + mi * 16 + quad + half * 8;
#pragma unroll
            for (int ni = 0; ni < NI; ni++) {
                long long col = col0 + wn + ni * 8 + qt * 2;
                float v0 = acc[mi][ni][half * 2 + 0];
                float v1 = acc[mi][ni][half * 2 + 1];
                if (EPI >= 1) { v0 += bias[col]; v1 += bias[col + 1]; }
                if (EPI == 2) {
                    v0 += resid[row * ldr + col];
                    v1 += resid[row * ldr + col + 1];
                }
                if (RND) { v0 = f2tf(v0); v1 = f2tf(v1); }
                if (EPI == 3) {
                    int bb = (int)(row >> 10), ss = (int)(row & 1023);
                    int hh = (int)(col >> 6), dd = (int)(col & 63);
                    ((float*)C)[((((long long)bb * NH + hh) * D + dd) << 10) + ss] = v0;
                    hh = (int)((col + 1) >> 6); dd = (int)((col + 1) & 63);
                    ((float*)C)[((((long long)bb * NH + hh) * D + dd) << 10) + ss] = v1;
                } else if (sizeof(OutT) == 2) {
                    *reinterpret_cast<__half2*>((__half*)C + row * ldc + col) =
                        __floats2half2_rn(v0, v1);
                } else {
                    *reinterpret_cast<float2*>((float*)C + row * ldc + col) =
                        make_float2(v0, v1);
                }
            }
        }
    }
}

// -------- merged projection kernel: 128x128 tiles, 2 CTAs/SM --------
__global__ void __launch_bounds__(256, 2) k_proj(
    const float* __restrict__ hs, const float* __restrict__ rel,
    const float* __restrict__ Wq, const float* __restrict__ bq,
    const float* __restrict__ Wk, const float* __restrict__ bk,
    const float* __restrict__ Wv, const float* __restrict__ bv)
{
    int y = blockIdx.y;
    int col0 = blockIdx.x * 128;
    if (y < 32)
        gemm_body<1, 128, 128, true, true, true>(hs, HID, Wq, HID, bq, nullptr, 0, g_q, HID, HID, y * 128, col0);
    else if (y < 64)
        gemm_body<1, 128, 128, true, true, true>(hs, HID, Wk, HID, bk, nullptr, 0, g_k, HID, HID, (y - 32) * 128, col0);
    else if (y < 96)
        gemm_body<3, 128, 128, true, true, true>(hs, HID, Wv, HID, bv, nullptr, 0, g_v, HID, HID, (y - 64) * 128, col0);
    else if (y < 100)
        gemm_body<1, 128, 128, true, true, true>(rel, HID, Wk, HID, bk, nullptr, 0, g_posk, HID, HID, (y - 96) * 128, col0);
    else
        gemm_body<1, 128, 128, true, true, true>(rel, HID, Wq, HID, bq, nullptr, 0, g_posq, HID, HID, (y - 100) * 128, col0);
}

// -------- pos-att: c2p [h][s][bucket] and p2cT [h][bucket][t], fp16, 2 CTAs/SM --------
__global__ void __launch_bounds__(256, 2) k_posatt() {
    int z = blockIdx.x;
    if (z < 1536) {
        int h = z >> 7, r = z & 127;
        gemm_body<0, 128, 128, false, false, false>(g_q + h * D, HID, g_posk + h * D, HID, nullptr, nullptr, 0,
                          g_c2p + (size_t)h * BS * POS, POS, D,
                          (r >> 2) * 128, (r & 3) * 128);
    } else {
        z -= 1536;
        int h = z >> 7, r = z & 127;
        gemm_body<0, 128, 128, false, false, false>(g_posq + h * D, HID, g_k + h * D, HID, nullptr, nullptr, 0,
                          g_p2cT + (size_t)h * POS * BS, BS, D,
                          (r >> 5) * 128, (r & 31) * 128);
    }
}

// ======== FUSED scores + in-loop gathers + softmax -> probs (unchanged from R11) ========
__global__ void __launch_bounds__(512, 1) k_fused_scores(float* __restrict__ probs) {
    extern __shared__ float dyn[];
    float* Qs    = dyn;                       // [32][68]
    float* Ks    = Qs + 32 * 68;              // [6][64][68] ring
    float* red_m = Ks + 6 * 64 * 68;          // [32][8]
    float* red_s = red_m + 256;               // [32][8]

    int s0 = blockIdx.x * 32;
    int bh = blockIdx.y;
    int b = bh / NH, h = bh % NH;
    int tid = threadIdx.x;
    int w = tid >> 5, lane = tid & 31;
    int quad = lane >> 2, qt = lane & 3;
    int wm = (w >> 3) * 16;
    int wn = (w & 7) * 8;
    int nw = w & 7;

    const float* kptr = g_k + ((long long)b * SEQ) * HID + h * D;
    unsigned ks_base = (unsigned)__cvta_generic_to_shared(Ks);

    int r0 = tid >> 4, c0 = (tid & 15) << 2;
    int r1 = (tid + 512) >> 4, c1 = ((tid + 512) & 15) << 2;

    auto issue_k = [&](int cc) {
        int slot = cc % 6;
        const float* srcb = kptr + (long long)cc * 64 * HID;
        cp_async16(ks_base + (unsigned)(((slot * 64 + r0) * 68 + c0) * 4),
                   srcb + (long long)r0 * HID + c0);
        cp_async16(ks_base + (unsigned)(((slot * 64 + r1) * 68 + c1) * 4),
                   srcb + (long long)r1 * HID + c1);
        asm volatile("cp.async.commit_group;\n");
    };

    issue_k(0); issue_k(1); issue_k(2); issue_k(3);

    {
        int m = tid >> 4, kq = (tid & 15) * 4;
        *reinterpret_cast<float4*>(&Qs[m * 68 + kq]) =
            *reinterpret_cast<const float4*>(
                g_q + ((long long)(b * SEQ + s0 + m)) * HID + h * D + kq);
    }
    __syncthreads();

    unsigned areg[8][4];
#pragma unroll
    for (int ks = 0; ks < 8; ks++) {
        int kk = ks * 8;
        areg[ks][0] = __float_as_uint(Qs[(wm + quad) * 68 + kk + qt]);
        areg[ks][1] = __float_as_uint(Qs[(wm + quad + 8) * 68 + kk + qt]);
        areg[ks][2] = __float_as_uint(Qs[(wm + quad) * 68 + kk + qt + 4]);
        areg[ks][3] = __float_as_uint(Qs[(wm + quad + 8) * 68 + kk + qt + 4]);
    }

    float acc[16][4];
#pragma unroll
    for (int f = 0; f < 16; f++)
#pragma unroll
        for (int j = 0; j < 4; j++) acc[f][j] = 0.0f;

    const float inv = rsqrtf(192.0f);
    int sl0 = wm + quad;
    long long c2pb0 = ((long long)h * BS + b * SEQ + s0 + sl0) * POS;
    long long c2pb1 = c2pb0 + 8LL * POS;
    long long pTb = (long long)h * POS * BS + (long long)b * SEQ;
    float rmax[2] = {-1e30f, -1e30f};

    auto do_chunk = [&](int c) {
        int slot = c % 6;
        const float* kb = &Ks[(slot * 64 + wn + quad) * 68];
#pragma unroll
        for (int ks = 0; ks < 8; ks++) {
            unsigned bb[2];
            bb[0] = __float_as_uint(kb[ks * 8 + qt]);
            bb[1] = __float_as_uint(kb[ks * 8 + qt + 4]);
            mma_tf32(acc[c], areg[ks], bb);
        }
        int colb = c * 64 + wn + qt * 2;
#pragma unroll
        for (int rh = 0; rh < 2; rh++) {
            int s = s0 + sl0 + rh * 8;
            long long cb = rh ? c2pb1 : c2pb0;
#pragma unroll
            for (int e = 0; e < 2; e++) {
                int t = colb + e;
                int ci = __ldg(&g_c2pidx[s - t + 1023]);
                float x = acc[c][rh * 2 + e]
                        + __half2float(__ldg(&g_c2p[cb + ci]))
                        + __half2float(__ldg(&g_p2cT[pTb + (long long)ci * BS + t]));
                x *= inv;
                acc[c][rh * 2 + e] = x;
                rmax[rh] = fmaxf(rmax[rh], x);
            }
        }
    };

#pragma unroll
    for (int c = 0; c < 16; c += 2) {
        asm volatile("cp.async.wait_group %0;\n" :: "n"(2));
        __syncthreads();
        if (c + 4 < 16) issue_k(c + 4);
        else            asm volatile("cp.async.commit_group;\n");
        if (c + 5 < 16) issue_k(c + 5);
        else            asm volatile("cp.async.commit_group;\n");
        do_chunk(c);
        do_chunk(c + 1);
    }

#pragma unroll
    for (int o = 1; o <= 2; o <<= 1) {
        rmax[0] = fmaxf(rmax[0], __shfl_xor_sync(0xffffffffu, rmax[0], o));
        rmax[1] = fmaxf(rmax[1], __shfl_xor_sync(0xffffffffu, rmax[1], o));
    }
    if (qt == 0) { red_m[sl0 * 8 + nw] = rmax[0]; red_m[(sl0 + 8) * 8 + nw] = rmax[1]; }
    __syncthreads();
    float mrow[2];
#pragma unroll
    for (int rh = 0; rh < 2; rh++) {
        float m = red_m[(sl0 + rh * 8) * 8];
#pragma unroll
        for (int j = 1; j < 8; j++) m = fmaxf(m, red_m[(sl0 + rh * 8) * 8 + j]);
        mrow[rh] = m;
    }
    float rsum[2] = {0.0f, 0.0f};
#pragma unroll
    for (int f = 0; f < 16; f++)
#pragma unroll
        for (int rh = 0; rh < 2; rh++)
#pragma unroll
            for (int e = 0; e < 2; e++) {
                float v = __expf(acc[f][rh * 2 + e] - mrow[rh]);
                acc[f][rh * 2 + e] = v;
                rsum[rh] += v;
            }
#pragma unroll
    for (int o = 1; o <= 2; o <<= 1) {
        rsum[0] += __shfl_xor_sync(0xffffffffu, rsum[0], o);
        rsum[1] += __shfl_xor_sync(0xffffffffu, rsum[1], o);
    }
    if (qt == 0) { red_s[sl0 * 8 + nw] = rsum[0]; red_s[(sl0 + 8) * 8 + nw] = rsum[1]; }
    __syncthreads();
    float rinv[2];
#pragma unroll
    for (int rh = 0; rh < 2; rh++) {
        float sum = 0.0f;
#pragma unroll
        for (int j = 0; j < 8; j++) sum += red_s[(sl0 + rh * 8) * 8 + j];
        rinv[rh] = 1.0f / sum;
    }
#pragma unroll
    for (int rh = 0; rh < 2; rh++) {
        float* prow = probs + ((long long)bh * SEQ + s0 + sl0 + rh * 8) * SEQ;
#pragma unroll
        for (int f = 0; f < 16; f++) {
            int colb = f * 64 + wn + qt * 2;
            *reinterpret_cast<float2*>(&prow[colb]) =
                make_float2(acc[f][rh * 2] * rinv[rh], acc[f][rh * 2 + 1] * rinv[rh]);
        }
    }
}

// ctx = probs @ vT, 2 CTAs/SM
__global__ void __launch_bounds__(256, 2) k_ctx(const float* __restrict__ probs) {
    int z = blockIdx.y;
    int b = z / NH, h = z % NH;
    gemm_body<0, 128, 64, true, false, true>(probs + (size_t)z * SEQ * SEQ, SEQ,
                     g_v + (size_t)z * D * SEQ, SEQ,
                     nullptr, nullptr, 0,
                     g_ctx + (size_t)(b * SEQ) * HID + h * D, HID, SEQ,
                     blockIdx.x * 128, 0);
}

__global__ void __launch_bounds__(256, 2) k_out(const float* __restrict__ hs,
                                                const float* __restrict__ Wo, const float* __restrict__ bo) {
    gemm_body<2, 128, 128, false, true, false>(g_ctx, HID, Wo, HID, bo, hs, HID, g_pre, HID, HID,
                      blockIdx.y * 128, blockIdx.x * 128);
}

// -------- layernorm over rows of g_pre --------
__global__ void ln_kernel(const float* __restrict__ lnw, const float* __restrict__ lnb,
                          float* __restrict__ out) {
    int row = blockIdx.x;
    const float* x = g_pre + (long long)row * HID;
    float* o = out + (long long)row * HID;
    int tid = threadIdx.x;
    __shared__ float red[8];
    float v[3];
    float s = 0.0f;
#pragma unroll
    for (int k = 0; k < 3; k++) {
        v[k] = x[tid + k * 256];
        s += v[k];
    }
#pragma unroll
    for (int o2 = 16; o2; o2 >>= 1) s += __shfl_xor_sync(0xffffffffu, s, o2);
    if ((tid & 31) == 0) red[tid >> 5] = s;
    __syncthreads();
    if (tid == 0) {
        float x2 = 0.0f;
#pragma unroll
        for (int i = 0; i < 8; i++) x2 += red[i];
        red[0] = x2;
    }
    __syncthreads();
    float mu = red[0] / (float)HID;
    __syncthreads();
    float sq = 0.0f;
#pragma unroll
    for (int k = 0; k < 3; k++) {
        float d = v[k] - mu;
        sq += d * d;
    }
#pragma unroll
    for (int o2 = 16; o2; o2 >>= 1) sq += __shfl_xor_sync(0xffffffffu, sq, o2);
    if ((tid & 31) == 0) red[tid >> 5] = sq;
    __syncthreads();
    if (tid == 0) {
        float x2 = 0.0f;
#pragma unroll
        for (int i = 0; i < 8; i++) x2 += red[i];
        red[0] = x2;
    }
    __syncthreads();
    float var = red[0] / (float)HID;
    float rstd = 1.0f / sqrtf(var + 1e-7f);
#pragma unroll
    for (int k = 0; k < 3; k++) {
        int c = tid + k * 256;
        o[c] = lnw[c] * (v[k] - mu) * rstd + lnb[c];
    }
}

extern "C" void kernel_launch(void* const* d_in, const int* in_sizes, int n_in,
                              void* d_out, int out_size) {
    const float* hs  = (const float*)d_in[0];
    const float* rel = (const float*)d_in[1];
    const float* Wq  = (const float*)d_in[2];
    const float* bq  = (const float*)d_in[3];
    const float* Wk  = (const float*)d_in[4];
    const float* bk  = (const float*)d_in[5];
    const float* Wv  = (const float*)d_in[6];
    const float* bv  = (const float*)d_in[7];
    const float* Wo  = (const float*)d_in[8];
    const float* bo  = (const float*)d_in[9];
    const float* lnw = (const float*)d_in[10];
    const float* lnb = (const float*)d_in[11];

    float* out   = (float*)d_out;
    float* probs = out + (size_t)BS * HID;

    const int GEMM_N128_SMEM = 4 * 256 * 20 * 4;  // 81920
    const int GEMM_N64_SMEM  = 4 * 192 * 20 * 4;  // 61440
    const int FUSED_SMEM = (32 * 68 + 6 * 64 * 68 + 512) * 4;  // 115200

    cudaFuncSetAttribute(k_proj,   cudaFuncAttributeMaxDynamicSharedMemorySize, GEMM_N128_SMEM);
    cudaFuncSetAttribute(k_posatt, cudaFuncAttributeMaxDynamicSharedMemorySize, GEMM_N128_SMEM);
    cudaFuncSetAttribute(k_out,    cudaFuncAttributeMaxDynamicSharedMemorySize, GEMM_N128_SMEM);
    cudaFuncSetAttribute(k_ctx,    cudaFuncAttributeMaxDynamicSharedMemorySize, GEMM_N64_SMEM);
    cudaFuncSetAttribute(k_fused_scores, cudaFuncAttributeMaxDynamicSharedMemorySize, FUSED_SMEM);

    relb_kernel<<<8, 256>>>();
    k_proj<<<dim3(HID / 128, 104), 256, GEMM_N128_SMEM>>>(hs, rel, Wq, bq, Wk, bk, Wv, bv);
    k_posatt<<<3072, 256, GEMM_N128_SMEM>>>();
    k_fused_scores<<<dim3(SEQ / 32, BAT * NH), 512, FUSED_SMEM>>>(probs);
    k_ctx<<<dim3(SEQ / 128, BAT * NH), 256, GEMM_N64_SMEM>>>(probs);
    k_out<<<dim3(HID / 128, BS / 128), 256, GEMM_N128_SMEM>>>(hs, Wo, bo);
    ln_kernel<<<BS, 256>>>(lnw, lnb, out);
}